// round 4
// baseline (speedup 1.0000x reference)
#include <cuda_runtime.h>
#include <stdint.h>

#define HW     1024
#define CH     256
#define BS     32
#define CAND   2048
#define NROWS  (BS*CAND)
#define MTILE  64
#define SROW   65          // padded row stride for [CH][SROW] activation tiles
#define KC     32          // k-chunk for weight staging
#define NBLK   (NROWS/MTILE)
#define SMEM_BYTES ((2*CH*SROW + 2*KC*CH)*4)

// ---------------- scratch (static device allocations are allowed) -----------
__device__ float g_t[BS*HW*CH];    // transposed gimage: [b][p][c], 128 MB
__device__ float g_wk[6*CH*CH];    // k-major weights:  [w][k][n], 1.5 MB

// ---------------- f32x2 helpers ---------------------------------------------
__device__ __forceinline__ uint64_t pack2(float lo, float hi) {
    uint64_t r; asm("mov.b64 %0, {%1,%2};" : "=l"(r) : "f"(lo), "f"(hi)); return r;
}
__device__ __forceinline__ void unpack2(uint64_t v, float& lo, float& hi) {
    asm("mov.b64 {%0,%1}, %2;" : "=f"(lo), "=f"(hi) : "l"(v));
}
#define FMA2(d, a, b) asm("fma.rn.f32x2 %0, %1, %2, %0;" : "+l"(d) : "l"(a), "l"(b))

// ---------------- cp.async helpers ------------------------------------------
__device__ __forceinline__ void cp16(void* sdst, const void* gsrc) {
    uint32_t s = (uint32_t)__cvta_generic_to_shared(sdst);
    asm volatile("cp.async.cg.shared.global [%0], [%1], 16;" :: "r"(s), "l"(gsrc));
}
__device__ __forceinline__ void cp_commit() { asm volatile("cp.async.commit_group;"); }
template <int N>
__device__ __forceinline__ void cp_wait() { asm volatile("cp.async.wait_group %0;" :: "n"(N)); }

// ---------------- kernel 1: transpose gimage [b][c][p] -> [b][p][c] ---------
__global__ void transpose_kernel(const float* __restrict__ g) {
    __shared__ float tile[32][33];
    int b  = blockIdx.z;
    int p0 = blockIdx.x * 32, c0 = blockIdx.y * 32;
    int tx = threadIdx.x, ty = threadIdx.y;          // 32 x 8
    const float* src = g   + (size_t)b * CH * HW;
    float*       dst = g_t + (size_t)b * HW * CH;
#pragma unroll
    for (int i = 0; i < 4; i++)
        tile[ty + i*8][tx] = src[(size_t)(c0 + ty + i*8) * HW + p0 + tx];
    __syncthreads();
#pragma unroll
    for (int i = 0; i < 4; i++)
        dst[(size_t)(p0 + ty + i*8) * CH + c0 + tx] = tile[tx][ty + i*8];
}

// ---------------- kernel 2: weight prep (center taps, k-major) --------------
// w0 = conv1 L0, w1 = conv2 L0, w2 = conv1 L1, w3 = conv2 L1, w4 = mlp1, w5 = mlp2
__global__ void prep_kernel(const float* __restrict__ c1, const float* __restrict__ c2,
                            const float* __restrict__ m1, const float* __restrict__ m2) {
    int gid = blockIdx.x * 256 + threadIdx.x;        // 0 .. 6*65536-1
    int w = gid >> 16;
    int e = gid & 65535;
    int k = e >> 8, n = e & 255;
    float v;
    if (w < 4) {
        const float* src = (w & 1) ? c2 : c1;        // [2][256][256][3][3]
        int layer = w >> 1;
        v = src[(size_t)layer * CH * CH * 9 + (size_t)(n * CH + k) * 9 + 4];
    } else {
        const float* src = (w == 4) ? m1 : m2;       // [256][256]
        v = src[n * CH + k];
    }
    g_wk[(size_t)w * 65536 + e] = v;                 // [k][n]
}

// ---------------- fused main kernel -----------------------------------------
// Tile GEMM: out[m][n] = sum_k src[k][m] * W[k][n], M=64, N=256, K=256.
// Thread (tm,tn): rows tm*4..tm*4+3, col pairs 2*(tn+16j), j=0..7.
__device__ __forceinline__ void gemm256(const float* __restrict__ src,
                                        float* __restrict__ wbuf,
                                        const float* __restrict__ wg,
                                        uint64_t acc[4][8], int tid) {
    const int tm = tid >> 4, tn = tid & 15;
#pragma unroll
    for (int r = 0; r < 4; r++)
#pragma unroll
        for (int j = 0; j < 8; j++) acc[r][j] = 0ull;

    // prefetch chunk 0
    {
        const float* gsrc = wg;
#pragma unroll
        for (int i = 0; i < 8; i++)
            cp16(wbuf + (i * 256 + tid) * 4, gsrc + (i * 256 + tid) * 4);
        cp_commit();
    }
#pragma unroll 1
    for (int ci = 0; ci < 8; ci++) {
        if (ci < 7) {
            const float* gsrc = wg + (size_t)(ci + 1) * KC * CH;
            float* sdst = wbuf + ((ci + 1) & 1) * KC * CH;
#pragma unroll
            for (int i = 0; i < 8; i++)
                cp16(sdst + (i * 256 + tid) * 4, gsrc + (i * 256 + tid) * 4);
            cp_commit();
            cp_wait<1>();
        } else {
            cp_wait<0>();
        }
        __syncthreads();
        const float* wb = wbuf + (ci & 1) * KC * CH;
        const float* sx = src + ci * KC * SROW + tm * 4;
#pragma unroll 8
        for (int kk = 0; kk < KC; kk++) {
            float x0 = sx[kk * SROW + 0], x1 = sx[kk * SROW + 1];
            float x2 = sx[kk * SROW + 2], x3 = sx[kk * SROW + 3];
            uint64_t xp0 = pack2(x0, x0), xp1 = pack2(x1, x1);
            uint64_t xp2 = pack2(x2, x2), xp3 = pack2(x3, x3);
            const float* wr = wb + kk * CH;
#pragma unroll
            for (int j = 0; j < 8; j++) {
                uint64_t wv = *reinterpret_cast<const uint64_t*>(wr + 2 * (tn + 16 * j));
                FMA2(acc[0][j], xp0, wv);
                FMA2(acc[1][j], xp1, wv);
                FMA2(acc[2][j], xp2, wv);
                FMA2(acc[3][j], xp3, wv);
            }
        }
        __syncthreads();   // all reads of wbuf[ci&1] done before next refill
    }
}

// GroupNorm(32 groups of 8) + SiLU over the 64x256 tile (k-major layout).
__device__ __forceinline__ void gn_silu(const float* __restrict__ src,
                                        float* __restrict__ dst,
                                        const float* __restrict__ gw,
                                        const float* __restrict__ gb, int tid) {
    __syncthreads();
#pragma unroll 1
    for (int it = 0; it < 8; it++) {
        int t = tid + 256 * it;           // (row, group) task, 2048 total
        int m = t & 63, g = t >> 6;
        float v[8]; float s = 0.f;
#pragma unroll
        for (int c = 0; c < 8; c++) { v[c] = src[(g * 8 + c) * SROW + m]; s += v[c]; }
        float mean = s * 0.125f;
        float var = 0.f;
#pragma unroll
        for (int c = 0; c < 8; c++) { float d = v[c] - mean; var += d * d; }
        var *= 0.125f;
        float rs = rsqrtf(var + 1e-5f);
#pragma unroll
        for (int c = 0; c < 8; c++) {
            float xn = (v[c] - mean) * rs * gw[g * 8 + c] + gb[g * 8 + c];
            dst[(g * 8 + c) * SROW + m] = xn * (1.f / (1.f + __expf(-xn)));
        }
    }
    __syncthreads();
}

__global__ __launch_bounds__(256) void main_kernel(
    const int*   __restrict__ pts,
    const float* __restrict__ gn1w, const float* __restrict__ gn1b,
    const float* __restrict__ c1b,
    const float* __restrict__ gn2w, const float* __restrict__ gn2b,
    const float* __restrict__ c2b,
    const float* __restrict__ clsw, const float* __restrict__ clsb,
    const float* __restrict__ mb1,  const float* __restrict__ mb2,
    const float* __restrict__ mw3,  const float* __restrict__ mb3,
    float* __restrict__ out) {
    extern __shared__ float smem[];
    float* xs   = smem;                   // [CH][SROW] current x (residual)
    float* ts   = smem + CH * SROW;       // [CH][SROW] temp activations
    float* wbuf = smem + 2 * CH * SROW;   // [2][KC][CH] weight chunks
    __shared__ int lins[64];

    int tid = threadIdx.x;
    int tm = tid >> 4, tn = tid & 15;
    int row_base = blockIdx.x * MTILE;

    // gather offsets: lin = (pts_y/8)*32 + pts_x/8
    if (tid < 64) {
        int r  = row_base + tid;
        int p0 = pts[r * 2 + 0], p1 = pts[r * 2 + 1];
        int b  = r >> 11;
        lins[tid] = (b * HW + ((p0 >> 3) * 32 + (p1 >> 3))) * CH;
    }
    __syncthreads();
    // gather rows (thread = channel; coalesced reads from transposed image)
#pragma unroll 4
    for (int m = 0; m < MTILE; m++)
        xs[tid * SROW + m] = g_t[lins[m] + tid];
    __syncthreads();

    uint64_t acc[4][8];

    // ---- two residual blocks ----
#pragma unroll 1
    for (int L = 0; L < 2; L++) {
        gn_silu(xs, ts, gn1w + L * CH, gn1b + L * CH, tid);
        gemm256(ts, wbuf, g_wk + (size_t)(L * 2 + 0) * 65536, acc, tid);
#pragma unroll
        for (int r = 0; r < 4; r++) {
            int m = tm * 4 + r;
#pragma unroll
            for (int j = 0; j < 8; j++) {
                int n = 2 * (tn + 16 * j);
                float f0, f1; unpack2(acc[r][j], f0, f1);
                ts[n * SROW + m]       = f0 + c1b[L * CH + n];
                ts[(n + 1) * SROW + m] = f1 + c1b[L * CH + n + 1];
            }
        }
        gn_silu(ts, ts, gn2w + L * CH, gn2b + L * CH, tid);
        gemm256(ts, wbuf, g_wk + (size_t)(L * 2 + 1) * 65536, acc, tid);
#pragma unroll
        for (int r = 0; r < 4; r++) {
            int m = tm * 4 + r;
#pragma unroll
            for (int j = 0; j < 8; j++) {
                int n = 2 * (tn + 16 * j);
                float f0, f1; unpack2(acc[r][j], f0, f1);
                xs[n * SROW + m]       += f0 + c2b[L * CH + n];
                xs[(n + 1) * SROW + m] += f1 + c2b[L * CH + n + 1];
            }
        }
        __syncthreads();
    }

    // ---- MLP layer 1: ts = relu(xs @ w4 + b1) ----
    gemm256(xs, wbuf, g_wk + (size_t)4 * 65536, acc, tid);
#pragma unroll
    for (int r = 0; r < 4; r++) {
        int m = tm * 4 + r;
#pragma unroll
        for (int j = 0; j < 8; j++) {
            int n = 2 * (tn + 16 * j);
            float f0, f1; unpack2(acc[r][j], f0, f1);
            ts[n * SROW + m]       = fmaxf(f0 + mb1[n], 0.f);
            ts[(n + 1) * SROW + m] = fmaxf(f1 + mb1[n + 1], 0.f);
        }
    }
    __syncthreads();
    // ---- MLP layer 2: ts = relu(ts @ w5 + b2) ----
    gemm256(ts, wbuf, g_wk + (size_t)5 * 65536, acc, tid);
#pragma unroll
    for (int r = 0; r < 4; r++) {
        int m = tm * 4 + r;
#pragma unroll
        for (int j = 0; j < 8; j++) {
            int n = 2 * (tn + 16 * j);
            float f0, f1; unpack2(acc[r][j], f0, f1);
            ts[n * SROW + m]       = fmaxf(f0 + mb2[n], 0.f);
            ts[(n + 1) * SROW + m] = fmaxf(f1 + mb2[n + 1], 0.f);
        }
    }
    __syncthreads();

    // ---- heads: cls (from xs) and box (from ts) ----
    int m = tid & 63, slot = tid >> 6;   // 4 threads per row
    float a3 = 0.f;
#pragma unroll 8
    for (int k = 0; k < CH; k++) a3 += ts[k * SROW + m] * mw3[slot * CH + k];
    a3 += mb3[slot];
    out[131072 + (size_t)(row_base + m) * 4 + slot] = 1.f / (1.f + __expf(-a3));
    if (slot < 2) {
        float al = 0.f;
#pragma unroll 8
        for (int k = 0; k < CH; k++) al += xs[k * SROW + m] * clsw[slot * CH + k];
        out[(size_t)(row_base + m) * 2 + slot] = al + clsb[slot];
    }
}

// ---------------- launch ------------------------------------------------------
extern "C" void kernel_launch(void* const* d_in, const int* in_sizes, int n_in,
                              void* d_out, int out_size) {
    const float* gimage = (const float*)d_in[0];
    const int*   pts    = (const int*)  d_in[1];
    const float* gn1w   = (const float*)d_in[2];
    const float* gn1b   = (const float*)d_in[3];
    const float* c1w    = (const float*)d_in[4];
    const float* c1b    = (const float*)d_in[5];
    const float* gn2w   = (const float*)d_in[6];
    const float* gn2b   = (const float*)d_in[7];
    const float* c2w    = (const float*)d_in[8];
    const float* c2b    = (const float*)d_in[9];
    const float* clsw   = (const float*)d_in[10];
    const float* clsb   = (const float*)d_in[11];
    const float* mw1    = (const float*)d_in[12];
    const float* mb1    = (const float*)d_in[13];
    const float* mw2    = (const float*)d_in[14];
    const float* mb2    = (const float*)d_in[15];
    const float* mw3    = (const float*)d_in[16];
    const float* mb3    = (const float*)d_in[17];
    float* out = (float*)d_out;

    cudaFuncSetAttribute(main_kernel, cudaFuncAttributeMaxDynamicSharedMemorySize,
                         SMEM_BYTES);

    dim3 tgrid(HW / 32, CH / 32, BS), tblk(32, 8);
    transpose_kernel<<<tgrid, tblk>>>(gimage);
    prep_kernel<<<(6 * 65536) / 256, 256>>>(c1w, c2w, mw1, mw2);
    main_kernel<<<NBLK, 256, SMEM_BYTES>>>(pts, gn1w, gn1b, c1b, gn2w, gn2b, c2b,
                                           clsw, clsb, mb1, mb2, mw3, mb3, out);
}

// round 6
// speedup vs baseline: 1.8361x; 1.8361x over previous
#include <cuda_runtime.h>
#include <cuda_bf16.h>
#include <stdint.h>

#define HW 1024
#define CH 256
#define BS 32
#define NROWS 65536
#define MT 64
#define NBLK (NROWS/MT)

#define OFF_X   0                 // fp32 [64][264]
#define OFF_AH  67584             // bf16 [64][264]
#define OFF_AL  101376            // bf16 [64][264]
#define OFF_B   135168            // 2 x 32KB weight chunks
#define OFF_RED 200704            // 64*16 f32 head partials
#define OFF_W3  204800            // mw3 4x256
#define OFF_CW  208896            // clsw 2x256
#define OFF_LIN 210944            // 64 ints
#define SMEM_TOTAL 211456

__device__ float g_t[(size_t)BS*HW*CH];                  // [b][p][c]
__device__ __align__(16) unsigned char g_wb[(size_t)6*8*32768]; // frag-packed weights

// ---------- helpers ----------
__device__ __forceinline__ uint32_t s2u(const void* p){
    uint32_t a; asm("{ .reg .u64 t; cvta.to.shared.u64 t, %1; cvt.u32.u64 %0, t; }":"=r"(a):"l"(p)); return a;
}
__device__ __forceinline__ void cp16(uint32_t sdst, const void* g){
    asm volatile("cp.async.cg.shared.global [%0], [%1], 16;"::"r"(sdst),"l"(g));
}
__device__ __forceinline__ uint32_t lds32(uint32_t a){
    uint32_t v; asm volatile("ld.shared.b32 %0,[%1];":"=r"(v):"r"(a)); return v;
}
__device__ __forceinline__ void lds64(uint32_t a,uint32_t&x,uint32_t&y){
    asm volatile("ld.shared.v2.b32 {%0,%1},[%2];":"=r"(x),"=r"(y):"r"(a));
}
__device__ __forceinline__ void sts32(uint32_t a,uint32_t v){
    asm volatile("st.shared.b32 [%0],%1;"::"r"(a),"r"(v));
}
__device__ __forceinline__ void lds2f(uint32_t a,float&x,float&y){
    asm volatile("ld.shared.v2.f32 {%0,%1},[%2];":"=f"(x),"=f"(y):"r"(a));
}
__device__ __forceinline__ void sts2f(uint32_t a,float x,float y){
    asm volatile("st.shared.v2.f32 [%0],{%1,%2};"::"r"(a),"f"(x),"f"(y));
}
__device__ __forceinline__ float silu(float x){ return x/(1.f+__expf(-x)); }
__device__ __forceinline__ uint32_t packbf(float f0,float f1){
    __nv_bfloat162 t=__floats2bfloat162_rn(f0,f1); return *(uint32_t*)&t;
}
__device__ __forceinline__ void split2(float f0,float f1,uint32_t&h,uint32_t&l){
    __nv_bfloat16 b0=__float2bfloat16_rn(f0), b1=__float2bfloat16_rn(f1);
    h=(uint32_t)*(uint16_t*)&b0 | ((uint32_t)*(uint16_t*)&b1<<16);
    l=packbf(f0-__bfloat162float(b0), f1-__bfloat162float(b1));
}
__device__ __forceinline__ void mma16816(float* d,const uint32_t* a,uint32_t b0,uint32_t b1){
    asm volatile("mma.sync.aligned.m16n8k16.row.col.f32.bf16.bf16.f32 "
        "{%0,%1,%2,%3}, {%4,%5,%6,%7}, {%8,%9}, {%0,%1,%2,%3};"
        : "+f"(d[0]),"+f"(d[1]),"+f"(d[2]),"+f"(d[3])
        : "r"(a[0]),"r"(a[1]),"r"(a[2]),"r"(a[3]),"r"(b0),"r"(b1));
}
// GN over 8 channels spread across the 4 quad lanes (2 per lane)
#define GNPAIR(D0,D1,GW,GB,N0) { \
    float s_=(D0)+(D1); s_+=__shfl_xor_sync(0xffffffffu,s_,1); s_+=__shfl_xor_sync(0xffffffffu,s_,2); \
    float mn_=s_*0.125f, e0_=(D0)-mn_, e1_=(D1)-mn_; \
    float vv_=e0_*e0_+e1_*e1_; vv_+=__shfl_xor_sync(0xffffffffu,vv_,1); vv_+=__shfl_xor_sync(0xffffffffu,vv_,2); \
    float rs_=rsqrtf(vv_*0.125f+1e-5f); \
    (D0)=silu(e0_*rs_*(GW)[N0]+(GB)[N0]); (D1)=silu(e1_*rs_*(GW)[(N0)+1]+(GB)[(N0)+1]); }

// ---------- kernel 1: transpose [b][c][p] -> [b][p][c] ----------
__global__ void transpose_kernel(const float* __restrict__ g){
    __shared__ float tile[32][33];
    int b=blockIdx.z, p0=blockIdx.x*32, c0=blockIdx.y*32;
    int tx=threadIdx.x, ty=threadIdx.y;
    const float* src=g+(size_t)b*CH*HW;
    float* dst=g_t+(size_t)b*HW*CH;
#pragma unroll
    for(int i=0;i<4;i++) tile[ty+i*8][tx]=src[(size_t)(c0+ty+i*8)*HW+p0+tx];
    __syncthreads();
#pragma unroll
    for(int i=0;i<4;i++) dst[(size_t)(p0+ty+i*8)*CH+c0+tx]=tile[tx][ty+i*8];
}

// ---------- kernel 2: weights -> bf16 hi/lo fragment-packed chunks ----------
// chunk (w,kc): [hi 16KB][lo 16KB]; frag (ks,nt): 32 lanes x uint2
__global__ void prep_kernel(const float* __restrict__ c1,const float* __restrict__ c2,
                            const float* __restrict__ m1,const float* __restrict__ m2){
    int gid=blockIdx.x*256+threadIdx.x;          // 98304 total
    int lane=gid&31, nt=(gid>>5)&31, ks=(gid>>10)&1, kc=(gid>>11)&7, w=gid>>14;
    int q=lane&3, g=lane>>2;
    int n=nt*8+g;
    int k0=kc*32+ks*16+q*2;
    float v0,v1,v2,v3;
    if(w<4){
        const float* s=(w&1)?c2:c1; int L=w>>1;
        const float* p=s+((size_t)(L*CH+n)*CH)*9+4;
        v0=p[(size_t)k0*9]; v1=p[(size_t)(k0+1)*9];
        v2=p[(size_t)(k0+8)*9]; v3=p[(size_t)(k0+9)*9];
    } else {
        const float* p=((w==4)?m1:m2)+(size_t)n*CH;
        v0=p[k0]; v1=p[k0+1]; v2=p[k0+8]; v3=p[k0+9];
    }
    uint32_t h0,l0,h1,l1;
    split2(v0,v1,h0,l0); split2(v2,v3,h1,l1);
    size_t base=(size_t)(w*8+kc)*32768;
    uint32_t fo=((uint32_t)(ks*32+nt)*32+lane)*8;
    *(uint2*)(g_wb+base+fo)        =make_uint2(h0,h1);
    *(uint2*)(g_wb+base+16384+fo)  =make_uint2(l0,l1);
}

// ---------- GEMM: D[64][256] += A[64][256] x W^T, 3-pass bf16 split ----------
__device__ __forceinline__ void run_gemm(int w,uint32_t smb,int tid,
                                         int mq,int nh,int g,int q,float d[16][4]){
#pragma unroll
    for(int i=0;i<16;i++){d[i][0]=0.f;d[i][1]=0.f;d[i][2]=0.f;d[i][3]=0.f;}
    {   const unsigned char* src=g_wb+(size_t)(w*8)*32768;
        uint32_t dst=smb+OFF_B;
#pragma unroll
        for(int j=0;j<8;j++) cp16(dst+j*4096+tid*16, src+j*4096+tid*16);
        asm volatile("cp.async.commit_group;");
    }
    uint32_t aH=smb+OFF_AH+(mq*16+g)*528;
    uint32_t aL=smb+OFF_AL+(mq*16+g)*528;
#pragma unroll 1
    for(int kc=0;kc<8;kc++){
        if(kc<7){
            const unsigned char* src=g_wb+(size_t)(w*8+kc+1)*32768;
            uint32_t dst=smb+OFF_B+((kc+1)&1)*32768;
#pragma unroll
            for(int j=0;j<8;j++) cp16(dst+j*4096+tid*16, src+j*4096+tid*16);
            asm volatile("cp.async.commit_group;");
            asm volatile("cp.async.wait_group 1;");
        } else asm volatile("cp.async.wait_group 0;");
        __syncthreads();
        uint32_t bb=smb+OFF_B+(kc&1)*32768;
#pragma unroll
        for(int ks=0;ks<2;ks++){
            int koff=(kc*32+ks*16+q*2)*2;
            uint32_t ah[4],al[4];
            ah[0]=lds32(aH+koff);       ah[1]=lds32(aH+koff+8*528);
            ah[2]=lds32(aH+koff+16);    ah[3]=lds32(aH+koff+8*528+16);
            al[0]=lds32(aL+koff);       al[1]=lds32(aL+koff+8*528);
            al[2]=lds32(aL+koff+16);    al[3]=lds32(aL+koff+8*528+16);
            uint32_t fb=bb+((uint32_t)(ks*32+nh*16)*32+(tid&31))*8;
#pragma unroll
            for(int i=0;i<16;i++){
                uint32_t bh0,bh1,bl0,bl1;
                lds64(fb+i*256,bh0,bh1);
                lds64(fb+16384+i*256,bl0,bl1);
                mma16816(d[i],ah,bh0,bh1);
                mma16816(d[i],ah,bl0,bl1);
                mma16816(d[i],al,bh0,bh1);
            }
        }
        __syncthreads();
    }
}

// ---------- fused main kernel ----------
__global__ __launch_bounds__(256,1) void main_kernel(
    const int* __restrict__ pts,
    const float* __restrict__ gn1w,const float* __restrict__ gn1b,
    const float* __restrict__ c1b,
    const float* __restrict__ gn2w,const float* __restrict__ gn2b,
    const float* __restrict__ c2b,
    const float* __restrict__ clsw,const float* __restrict__ clsb,
    const float* __restrict__ mb1,const float* __restrict__ mb2,
    const float* __restrict__ mw3,const float* __restrict__ mb3,
    float* __restrict__ out)
{
    extern __shared__ __align__(16) unsigned char smp[];
    uint32_t smb=s2u(smp);
    int tid=threadIdx.x, lane=tid&31, wid=tid>>5;
    int mq=wid&3, nh=wid>>2, g=lane>>2, q=lane&3;
    int row_base=blockIdx.x*MT;
    float* w3s=(float*)(smp+OFF_W3);
    float* cws=(float*)(smp+OFF_CW);
    float* red=(float*)(smp+OFF_RED);

    for(int i=tid;i<1024;i+=256) w3s[i]=mw3[i];
    for(int i=tid;i<512;i+=256)  cws[i]=clsw[i];
    if(tid<MT){
        int r=row_base+tid;
        int p0=pts[r*2], p1=pts[r*2+1];
        ((int*)(smp+OFF_LIN))[tid]=((r>>11)*HW+((p0>>3)*32+(p1>>3)))*CH;
    }
    __syncthreads();

    // gather -> xs(f32) ; GN1[0]+SiLU -> A(hi/lo)
    {
        int row=tid>>2, t4=tid&3;
        const float* src=g_t+((const int*)(smp+OFF_LIN))[row]+t4*64;
        float v[64];
#pragma unroll
        for(int i=0;i<16;i++) *(float4*)(v+i*4)=*(const float4*)(src+i*4);
        uint32_t xb=smb+OFF_X+row*1056+t4*256;
#pragma unroll
        for(int i=0;i<16;i++)
            asm volatile("st.shared.v4.f32 [%0],{%1,%2,%3,%4};"
                ::"r"(xb+i*16),"f"(v[i*4]),"f"(v[i*4+1]),"f"(v[i*4+2]),"f"(v[i*4+3]));
#pragma unroll
        for(int gr=0;gr<8;gr++){
            float s=0.f,vv=0.f;
#pragma unroll
            for(int j=0;j<8;j++) s+=v[gr*8+j];
            float mean=s*0.125f;
#pragma unroll
            for(int j=0;j<8;j++){float e=v[gr*8+j]-mean; vv+=e*e;}
            float rs=rsqrtf(vv*0.125f+1e-5f);
#pragma unroll
            for(int j=0;j<8;j++){
                int n=t4*64+gr*8+j;
                v[gr*8+j]=silu((v[gr*8+j]-mean)*rs*gn1w[n]+gn1b[n]);
            }
        }
        uint32_t ahb=smb+OFF_AH+row*528+t4*128;
        uint32_t alb=smb+OFF_AL+row*528+t4*128;
#pragma unroll
        for(int j2=0;j2<32;j2++){
            uint32_t h,l; split2(v[2*j2],v[2*j2+1],h,l);
            sts32(ahb+j2*4,h); sts32(alb+j2*4,l);
        }
    }
    __syncthreads();

    float d[16][4];
    int mg=mq*16+g;
    uint32_t ah_w=smb+OFF_AH+mg*528, al_w=smb+OFF_AL+mg*528;
    uint32_t xs_w=smb+OFF_X+mg*1056;

#pragma unroll 1
    for(int L=0;L<2;++L){
        run_gemm(L*2+0,smb,tid,mq,nh,g,q,d);               // conv1
        const float* b1=c1b+L*CH; const float* g2w=gn2w+L*CH; const float* g2b=gn2b+L*CH;
#pragma unroll
        for(int i=0;i<16;i++){
            int n0=(nh*16+i)*8+q*2;
            d[i][0]+=b1[n0]; d[i][1]+=b1[n0+1]; d[i][2]+=b1[n0]; d[i][3]+=b1[n0+1];
            GNPAIR(d[i][0],d[i][1],g2w,g2b,n0);
            GNPAIR(d[i][2],d[i][3],g2w,g2b,n0);
            uint32_t h,l;
            split2(d[i][0],d[i][1],h,l); sts32(ah_w+n0*2,h);       sts32(al_w+n0*2,l);
            split2(d[i][2],d[i][3],h,l); sts32(ah_w+8*528+n0*2,h); sts32(al_w+8*528+n0*2,l);
        }
        __syncthreads();

        run_gemm(L*2+1,smb,tid,mq,nh,g,q,d);               // conv2
        const float* b2=c2b+L*CH; const float* g1w=gn1w+CH; const float* g1b=gn1b+CH;
#pragma unroll
        for(int i=0;i<16;i++){
            int n0=(nh*16+i)*8+q*2;
            float x0,x1;
            lds2f(xs_w+n0*4,x0,x1);
            d[i][0]+=b2[n0]+x0; d[i][1]+=b2[n0+1]+x1;
            sts2f(xs_w+n0*4,d[i][0],d[i][1]);
            lds2f(xs_w+8*1056+n0*4,x0,x1);
            d[i][2]+=b2[n0]+x0; d[i][3]+=b2[n0+1]+x1;
            sts2f(xs_w+8*1056+n0*4,d[i][2],d[i][3]);
            if(L==0){ GNPAIR(d[i][0],d[i][1],g1w,g1b,n0); GNPAIR(d[i][2],d[i][3],g1w,g1b,n0); }
            uint32_t h,l;
            split2(d[i][0],d[i][1],h,l); sts32(ah_w+n0*2,h);       sts32(al_w+n0*2,l);
            split2(d[i][2],d[i][3],h,l); sts32(ah_w+8*528+n0*2,h); sts32(al_w+8*528+n0*2,l);
        }
        __syncthreads();
    }

    run_gemm(4,smb,tid,mq,nh,g,q,d);                       // mlp1
#pragma unroll
    for(int i=0;i<16;i++){
        int n0=(nh*16+i)*8+q*2;
        d[i][0]=fmaxf(d[i][0]+mb1[n0],0.f);   d[i][1]=fmaxf(d[i][1]+mb1[n0+1],0.f);
        d[i][2]=fmaxf(d[i][2]+mb1[n0],0.f);   d[i][3]=fmaxf(d[i][3]+mb1[n0+1],0.f);
        uint32_t h,l;
        split2(d[i][0],d[i][1],h,l); sts32(ah_w+n0*2,h);       sts32(al_w+n0*2,l);
        split2(d[i][2],d[i][3],h,l); sts32(ah_w+8*528+n0*2,h); sts32(al_w+8*528+n0*2,l);
    }
    __syncthreads();

    run_gemm(5,smb,tid,mq,nh,g,q,d);                       // mlp2
    {
        float bg[4]={0,0,0,0}, bh[4]={0,0,0,0};
#pragma unroll
        for(int i=0;i<16;i++){
            int n0=(nh*16+i)*8+q*2;
            float t0=fmaxf(d[i][0]+mb2[n0],0.f),  t1=fmaxf(d[i][1]+mb2[n0+1],0.f);
            float t2=fmaxf(d[i][2]+mb2[n0],0.f),  t3=fmaxf(d[i][3]+mb2[n0+1],0.f);
#pragma unroll
            for(int s=0;s<4;s++){
                float w0=w3s[s*256+n0], w1=w3s[s*256+n0+1];
                bg[s]+=t0*w0+t1*w1;
                bh[s]+=t2*w0+t3*w1;
            }
        }
#pragma unroll
        for(int s=0;s<4;s++){
            bg[s]+=__shfl_xor_sync(0xffffffffu,bg[s],1); bg[s]+=__shfl_xor_sync(0xffffffffu,bg[s],2);
            bh[s]+=__shfl_xor_sync(0xffffffffu,bh[s],1); bh[s]+=__shfl_xor_sync(0xffffffffu,bh[s],2);
        }
        if(q==0){
#pragma unroll
            for(int s=0;s<4;s++){
                red[mg*16+nh*8+s]=bg[s];
                red[(mg+8)*16+nh*8+s]=bh[s];
            }
        }
    }
    __syncthreads();

    // heads out
    if(tid<MT){
        size_t row=(size_t)row_base+tid;
#pragma unroll
        for(int s=0;s<4;s++){
            float a=red[tid*16+s]+red[tid*16+8+s]+mb3[s];
            out[131072+row*4+s]=1.f/(1.f+__expf(-a));
        }
    }
    {
        int row=tid>>2, t4=tid&3;
        uint32_t xb=smb+OFF_X+row*1056;
        float c0=0.f,c1=0.f;
#pragma unroll 16
        for(int i=0;i<64;i++){
            int k=t4+4*i;
            float xv=*(float*)(smp+OFF_X+row*1056+k*4);
            c0+=xv*cws[k]; c1+=xv*cws[256+k];
        }
        (void)xb;
        c0+=__shfl_xor_sync(0xffffffffu,c0,1); c0+=__shfl_xor_sync(0xffffffffu,c0,2);
        c1+=__shfl_xor_sync(0xffffffffu,c1,1); c1+=__shfl_xor_sync(0xffffffffu,c1,2);
        if(t4==0){
            size_t r=(size_t)row_base+row;
            out[r*2+0]=c0+clsb[0];
            out[r*2+1]=c1+clsb[1];
        }
    }
}

// ---------- launch ----------
extern "C" void kernel_launch(void* const* d_in, const int* in_sizes, int n_in,
                              void* d_out, int out_size){
    const float* gimage=(const float*)d_in[0];
    const int*   pts   =(const int*)  d_in[1];
    const float* gn1w=(const float*)d_in[2],  *gn1b=(const float*)d_in[3];
    const float* c1w =(const float*)d_in[4],  *c1b =(const float*)d_in[5];
    const float* gn2w=(const float*)d_in[6],  *gn2b=(const float*)d_in[7];
    const float* c2w =(const float*)d_in[8],  *c2b =(const float*)d_in[9];
    const float* clsw=(const float*)d_in[10], *clsb=(const float*)d_in[11];
    const float* mw1 =(const float*)d_in[12], *mb1 =(const float*)d_in[13];
    const float* mw2 =(const float*)d_in[14], *mb2 =(const float*)d_in[15];
    const float* mw3 =(const float*)d_in[16], *mb3 =(const float*)d_in[17];
    float* out=(float*)d_out;

    cudaFuncSetAttribute(main_kernel, cudaFuncAttributeMaxDynamicSharedMemorySize, SMEM_TOTAL);

    dim3 tgrid(HW/32, CH/32, BS), tblk(32,8);
    transpose_kernel<<<tgrid,tblk>>>(gimage);
    prep_kernel<<<384,256>>>(c1w,c2w,mw1,mw2);
    main_kernel<<<NBLK,256,SMEM_TOTAL>>>(pts,gn1w,gn1b,c1b,gn2w,gn2b,c2b,
                                         clsw,clsb,mb1,mb2,mw3,mb3,out);
}

// round 7
// speedup vs baseline: 2.2134x; 1.2055x over previous
#include <cuda_runtime.h>
#include <cuda_fp16.h>
#include <stdint.h>

#define HW 1024
#define CH 256
#define BS 32
#define NROWS 65536
#define MT 64
#define NBLK (NROWS/MT)

#define OFF_X   0                 // fp32 [64][264]
#define OFF_AH  67584             // fp16 [64][264]
#define OFF_AL  101376            // fp16 [64][264]
#define OFF_B   135168            // 2 x 16KB weight chunks
#define OFF_RED 167936
#define OFF_W3  172032
#define OFF_CW  176128
#define OFF_LIN 178176
#define SMEM_TOTAL 178688

__device__ float g_t[(size_t)BS*HW*CH];                       // [b][p][c]
__device__ __align__(16) unsigned char g_wb[(size_t)6*8*16384]; // frag-packed fp16 weights

// ---------- helpers ----------
__device__ __forceinline__ uint32_t s2u(const void* p){
    uint32_t a; asm("{ .reg .u64 t; cvta.to.shared.u64 t, %1; cvt.u32.u64 %0, t; }":"=r"(a):"l"(p)); return a;
}
__device__ __forceinline__ void cp16(uint32_t sdst, const void* g){
    asm volatile("cp.async.cg.shared.global [%0], [%1], 16;"::"r"(sdst),"l"(g));
}
__device__ __forceinline__ uint32_t lds32(uint32_t a){
    uint32_t v; asm volatile("ld.shared.b32 %0,[%1];":"=r"(v):"r"(a)); return v;
}
__device__ __forceinline__ void lds64(uint32_t a,uint32_t&x,uint32_t&y){
    asm volatile("ld.shared.v2.b32 {%0,%1},[%2];":"=r"(x),"=r"(y):"r"(a));
}
__device__ __forceinline__ void sts32(uint32_t a,uint32_t v){
    asm volatile("st.shared.b32 [%0],%1;"::"r"(a),"r"(v));
}
__device__ __forceinline__ void lds2f(uint32_t a,float&x,float&y){
    asm volatile("ld.shared.v2.f32 {%0,%1},[%2];":"=f"(x),"=f"(y):"r"(a));
}
__device__ __forceinline__ void sts2f(uint32_t a,float x,float y){
    asm volatile("st.shared.v2.f32 [%0],{%1,%2};"::"r"(a),"f"(x),"f"(y));
}
__device__ __forceinline__ float silu(float x){ return x/(1.f+__expf(-x)); }
// exact fp16 hi/lo split of a float pair
__device__ __forceinline__ void split2(float f0,float f1,uint32_t&h,uint32_t&l){
    __half2 H=__floats2half2_rn(f0,f1);
    h=*(uint32_t*)&H;
    float r0=f0-__half2float(__low2half(H));
    float r1=f1-__half2float(__high2half(H));
    __half2 L=__floats2half2_rn(r0,r1);
    l=*(uint32_t*)&L;
}
__device__ __forceinline__ void mma16816(float* d,const uint32_t* a,uint32_t b0,uint32_t b1){
    asm volatile("mma.sync.aligned.m16n8k16.row.col.f32.f16.f16.f32 "
        "{%0,%1,%2,%3}, {%4,%5,%6,%7}, {%8,%9}, {%0,%1,%2,%3};"
        : "+f"(d[0]),"+f"(d[1]),"+f"(d[2]),"+f"(d[3])
        : "r"(a[0]),"r"(a[1]),"r"(a[2]),"r"(a[3]),"r"(b0),"r"(b1));
}
// GN over 8 channels spread across the 4 quad lanes (2 per lane)
#define GNPAIR(D0,D1,GW,GB,N0) { \
    float s_=(D0)+(D1); s_+=__shfl_xor_sync(0xffffffffu,s_,1); s_+=__shfl_xor_sync(0xffffffffu,s_,2); \
    float mn_=s_*0.125f, e0_=(D0)-mn_, e1_=(D1)-mn_; \
    float vv_=e0_*e0_+e1_*e1_; vv_+=__shfl_xor_sync(0xffffffffu,vv_,1); vv_+=__shfl_xor_sync(0xffffffffu,vv_,2); \
    float rs_=rsqrtf(vv_*0.125f+1e-5f); \
    (D0)=silu(e0_*rs_*(GW)[N0]+(GB)[N0]); (D1)=silu(e1_*rs_*(GW)[(N0)+1]+(GB)[(N0)+1]); }

// ---------- kernel 1: transpose [b][c][p] -> [b][p][c] ----------
__global__ void transpose_kernel(const float* __restrict__ g){
    __shared__ float tile[32][33];
    int b=blockIdx.z, p0=blockIdx.x*32, c0=blockIdx.y*32;
    int tx=threadIdx.x, ty=threadIdx.y;
    const float* src=g+(size_t)b*CH*HW;
    float* dst=g_t+(size_t)b*HW*CH;
#pragma unroll
    for(int i=0;i<4;i++) tile[ty+i*8][tx]=src[(size_t)(c0+ty+i*8)*HW+p0+tx];
    __syncthreads();
#pragma unroll
    for(int i=0;i<4;i++) dst[(size_t)(p0+ty+i*8)*CH+c0+tx]=tile[tx][ty+i*8];
}

// ---------- kernel 2: weights -> single-fp16 fragment-packed chunks ----------
// chunk (w,kc) = 16KB; frag (ks,nt): 32 lanes x uint2
__global__ void prep_kernel(const float* __restrict__ c1,const float* __restrict__ c2,
                            const float* __restrict__ m1,const float* __restrict__ m2){
    int gid=blockIdx.x*256+threadIdx.x;          // 98304 total
    int lane=gid&31, nt=(gid>>5)&31, ks=(gid>>10)&1, kc=(gid>>11)&7, w=gid>>14;
    int q=lane&3, g=lane>>2;
    int n=nt*8+g;
    int k0=kc*32+ks*16+q*2;
    float v0,v1,v2,v3;
    if(w<4){
        const float* s=(w&1)?c2:c1; int L=w>>1;
        const float* p=s+((size_t)(L*CH+n)*CH)*9+4;
        v0=p[(size_t)k0*9]; v1=p[(size_t)(k0+1)*9];
        v2=p[(size_t)(k0+8)*9]; v3=p[(size_t)(k0+9)*9];
    } else {
        const float* p=((w==4)?m1:m2)+(size_t)n*CH;
        v0=p[k0]; v1=p[k0+1]; v2=p[k0+8]; v3=p[k0+9];
    }
    __half2 h01=__floats2half2_rn(v0,v1);
    __half2 h23=__floats2half2_rn(v2,v3);
    size_t base=(size_t)(w*8+kc)*16384;
    uint32_t fo=((uint32_t)(ks*32+nt)*32+lane)*8;
    *(uint2*)(g_wb+base+fo)=make_uint2(*(uint32_t*)&h01,*(uint32_t*)&h23);
}

// ---------- GEMM: D[64][256] = A[64][256] x W^T, 2-pass fp16 split ----------
__device__ __forceinline__ void run_gemm(int w,uint32_t smb,int tid,
                                         int mq,int nh,int g,int q,float d[16][4]){
#pragma unroll
    for(int i=0;i<16;i++){d[i][0]=0.f;d[i][1]=0.f;d[i][2]=0.f;d[i][3]=0.f;}
    {   const unsigned char* src=g_wb+(size_t)(w*8)*16384;
        uint32_t dst=smb+OFF_B;
#pragma unroll
        for(int j=0;j<4;j++) cp16(dst+j*4096+tid*16, src+j*4096+tid*16);
        asm volatile("cp.async.commit_group;");
    }
    uint32_t aH=smb+OFF_AH+(mq*16+g)*528;
    uint32_t aL=smb+OFF_AL+(mq*16+g)*528;
#pragma unroll 1
    for(int kc=0;kc<8;kc++){
        if(kc<7){
            const unsigned char* src=g_wb+(size_t)(w*8+kc+1)*16384;
            uint32_t dst=smb+OFF_B+((kc+1)&1)*16384;
#pragma unroll
            for(int j=0;j<4;j++) cp16(dst+j*4096+tid*16, src+j*4096+tid*16);
            asm volatile("cp.async.commit_group;");
            asm volatile("cp.async.wait_group 1;");
        } else asm volatile("cp.async.wait_group 0;");
        __syncthreads();
        uint32_t bb=smb+OFF_B+(kc&1)*16384;
#pragma unroll
        for(int ks=0;ks<2;ks++){
            int koff=(kc*32+ks*16+q*2)*2;
            uint32_t ah[4],al[4];
            ah[0]=lds32(aH+koff);       ah[1]=lds32(aH+koff+8*528);
            ah[2]=lds32(aH+koff+16);    ah[3]=lds32(aH+koff+8*528+16);
            al[0]=lds32(aL+koff);       al[1]=lds32(aL+koff+8*528);
            al[2]=lds32(aL+koff+16);    al[3]=lds32(aL+koff+8*528+16);
            uint32_t fb=bb+((uint32_t)(ks*32+nh*16)*32+(tid&31))*8;
#pragma unroll
            for(int i=0;i<16;i++){
                uint32_t b0,b1;
                lds64(fb+i*256,b0,b1);
                mma16816(d[i],ah,b0,b1);
                mma16816(d[i],al,b0,b1);
            }
        }
        __syncthreads();
    }
}

// ---------- fused main kernel ----------
__global__ __launch_bounds__(256,1) void main_kernel(
    const int* __restrict__ pts,
    const float* __restrict__ gn1w,const float* __restrict__ gn1b,
    const float* __restrict__ c1b,
    const float* __restrict__ gn2w,const float* __restrict__ gn2b,
    const float* __restrict__ c2b,
    const float* __restrict__ clsw,const float* __restrict__ clsb,
    const float* __restrict__ mb1,const float* __restrict__ mb2,
    const float* __restrict__ mw3,const float* __restrict__ mb3,
    float* __restrict__ out)
{
    extern __shared__ __align__(16) unsigned char smp[];
    uint32_t smb=s2u(smp);
    int tid=threadIdx.x, lane=tid&31, wid=tid>>5;
    int mq=wid&3, nh=wid>>2, g=lane>>2, q=lane&3;
    int row_base=blockIdx.x*MT;
    float* w3s=(float*)(smp+OFF_W3);
    float* cws=(float*)(smp+OFF_CW);
    float* red=(float*)(smp+OFF_RED);

    for(int i=tid;i<1024;i+=256) w3s[i]=mw3[i];
    for(int i=tid;i<512;i+=256)  cws[i]=clsw[i];
    if(tid<MT){
        int r=row_base+tid;
        int p0=pts[r*2], p1=pts[r*2+1];
        ((int*)(smp+OFF_LIN))[tid]=((r>>11)*HW+((p0>>3)*32+(p1>>3)))*CH;
    }
    __syncthreads();

    // gather -> xs(f32) ; GN1[0]+SiLU -> A(hi/lo)
    {
        int row=tid>>2, t4=tid&3;
        const float* src=g_t+((const int*)(smp+OFF_LIN))[row]+t4*64;
        float v[64];
#pragma unroll
        for(int i=0;i<16;i++) *(float4*)(v+i*4)=*(const float4*)(src+i*4);
        uint32_t xb=smb+OFF_X+row*1056+t4*256;
#pragma unroll
        for(int i=0;i<16;i++)
            asm volatile("st.shared.v4.f32 [%0],{%1,%2,%3,%4};"
                ::"r"(xb+i*16),"f"(v[i*4]),"f"(v[i*4+1]),"f"(v[i*4+2]),"f"(v[i*4+3]));
#pragma unroll
        for(int gr=0;gr<8;gr++){
            float s=0.f,vv=0.f;
#pragma unroll
            for(int j=0;j<8;j++) s+=v[gr*8+j];
            float mean=s*0.125f;
#pragma unroll
            for(int j=0;j<8;j++){float e=v[gr*8+j]-mean; vv+=e*e;}
            float rs=rsqrtf(vv*0.125f+1e-5f);
#pragma unroll
            for(int j=0;j<8;j++){
                int n=t4*64+gr*8+j;
                v[gr*8+j]=silu((v[gr*8+j]-mean)*rs*gn1w[n]+gn1b[n]);
            }
        }
        uint32_t ahb=smb+OFF_AH+row*528+t4*128;
        uint32_t alb=smb+OFF_AL+row*528+t4*128;
#pragma unroll
        for(int j2=0;j2<32;j2++){
            uint32_t h,l; split2(v[2*j2],v[2*j2+1],h,l);
            sts32(ahb+j2*4,h); sts32(alb+j2*4,l);
        }
    }
    __syncthreads();

    float d[16][4];
    int mg=mq*16+g;
    uint32_t ah_w=smb+OFF_AH+mg*528, al_w=smb+OFF_AL+mg*528;
    uint32_t xs_w=smb+OFF_X+mg*1056;

#pragma unroll 1
    for(int L=0;L<2;++L){
        run_gemm(L*2+0,smb,tid,mq,nh,g,q,d);               // conv1
        const float* b1=c1b+L*CH; const float* g2w=gn2w+L*CH; const float* g2b=gn2b+L*CH;
#pragma unroll
        for(int i=0;i<16;i++){
            int n0=(nh*16+i)*8+q*2;
            d[i][0]+=b1[n0]; d[i][1]+=b1[n0+1]; d[i][2]+=b1[n0]; d[i][3]+=b1[n0+1];
            GNPAIR(d[i][0],d[i][1],g2w,g2b,n0);
            GNPAIR(d[i][2],d[i][3],g2w,g2b,n0);
            uint32_t h,l;
            split2(d[i][0],d[i][1],h,l); sts32(ah_w+n0*2,h);       sts32(al_w+n0*2,l);
            split2(d[i][2],d[i][3],h,l); sts32(ah_w+8*528+n0*2,h); sts32(al_w+8*528+n0*2,l);
        }
        __syncthreads();

        run_gemm(L*2+1,smb,tid,mq,nh,g,q,d);               // conv2
        const float* b2=c2b+L*CH; const float* g1w=gn1w+CH; const float* g1b=gn1b+CH;
#pragma unroll
        for(int i=0;i<16;i++){
            int n0=(nh*16+i)*8+q*2;
            float x0,x1;
            lds2f(xs_w+n0*4,x0,x1);
            d[i][0]+=b2[n0]+x0; d[i][1]+=b2[n0+1]+x1;
            sts2f(xs_w+n0*4,d[i][0],d[i][1]);
            lds2f(xs_w+8*1056+n0*4,x0,x1);
            d[i][2]+=b2[n0]+x0; d[i][3]+=b2[n0+1]+x1;
            sts2f(xs_w+8*1056+n0*4,d[i][2],d[i][3]);
            if(L==0){ GNPAIR(d[i][0],d[i][1],g1w,g1b,n0); GNPAIR(d[i][2],d[i][3],g1w,g1b,n0); }
            uint32_t h,l;
            split2(d[i][0],d[i][1],h,l); sts32(ah_w+n0*2,h);       sts32(al_w+n0*2,l);
            split2(d[i][2],d[i][3],h,l); sts32(ah_w+8*528+n0*2,h); sts32(al_w+8*528+n0*2,l);
        }
        __syncthreads();
    }

    run_gemm(4,smb,tid,mq,nh,g,q,d);                       // mlp1
#pragma unroll
    for(int i=0;i<16;i++){
        int n0=(nh*16+i)*8+q*2;
        d[i][0]=fmaxf(d[i][0]+mb1[n0],0.f);   d[i][1]=fmaxf(d[i][1]+mb1[n0+1],0.f);
        d[i][2]=fmaxf(d[i][2]+mb1[n0],0.f);   d[i][3]=fmaxf(d[i][3]+mb1[n0+1],0.f);
        uint32_t h,l;
        split2(d[i][0],d[i][1],h,l); sts32(ah_w+n0*2,h);       sts32(al_w+n0*2,l);
        split2(d[i][2],d[i][3],h,l); sts32(ah_w+8*528+n0*2,h); sts32(al_w+8*528+n0*2,l);
    }
    __syncthreads();

    run_gemm(5,smb,tid,mq,nh,g,q,d);                       // mlp2
    {
        float bg[4]={0,0,0,0}, bh[4]={0,0,0,0};
#pragma unroll
        for(int i=0;i<16;i++){
            int n0=(nh*16+i)*8+q*2;
            float t0=fmaxf(d[i][0]+mb2[n0],0.f),  t1=fmaxf(d[i][1]+mb2[n0+1],0.f);
            float t2=fmaxf(d[i][2]+mb2[n0],0.f),  t3=fmaxf(d[i][3]+mb2[n0+1],0.f);
#pragma unroll
            for(int s=0;s<4;s++){
                float w0=w3s[s*256+n0], w1=w3s[s*256+n0+1];
                bg[s]+=t0*w0+t1*w1;
                bh[s]+=t2*w0+t3*w1;
            }
        }
#pragma unroll
        for(int s=0;s<4;s++){
            bg[s]+=__shfl_xor_sync(0xffffffffu,bg[s],1); bg[s]+=__shfl_xor_sync(0xffffffffu,bg[s],2);
            bh[s]+=__shfl_xor_sync(0xffffffffu,bh[s],1); bh[s]+=__shfl_xor_sync(0xffffffffu,bh[s],2);
        }
        if(q==0){
#pragma unroll
            for(int s=0;s<4;s++){
                red[mg*16+nh*8+s]=bg[s];
                red[(mg+8)*16+nh*8+s]=bh[s];
            }
        }
    }
    __syncthreads();

    // heads out
    if(tid<MT){
        size_t row=(size_t)row_base+tid;
#pragma unroll
        for(int s=0;s<4;s++){
            float a=red[tid*16+s]+red[tid*16+8+s]+mb3[s];
            out[131072+row*4+s]=1.f/(1.f+__expf(-a));
        }
    }
    {
        int row=tid>>2, t4=tid&3;
        float c0=0.f,c1=0.f;
#pragma unroll 16
        for(int i=0;i<64;i++){
            int k=t4+4*i;
            float xv=*(float*)(smp+OFF_X+row*1056+k*4);
            c0+=xv*cws[k]; c1+=xv*cws[256+k];
        }
        c0+=__shfl_xor_sync(0xffffffffu,c0,1); c0+=__shfl_xor_sync(0xffffffffu,c0,2);
        c1+=__shfl_xor_sync(0xffffffffu,c1,1); c1+=__shfl_xor_sync(0xffffffffu,c1,2);
        if(t4==0){
            size_t r=(size_t)row_base+row;
            out[r*2+0]=c0+clsb[0];
            out[r*2+1]=c1+clsb[1];
        }
    }
}

// ---------- launch ----------
extern "C" void kernel_launch(void* const* d_in, const int* in_sizes, int n_in,
                              void* d_out, int out_size){
    const float* gimage=(const float*)d_in[0];
    const int*   pts   =(const int*)  d_in[1];
    const float* gn1w=(const float*)d_in[2],  *gn1b=(const float*)d_in[3];
    const float* c1w =(const float*)d_in[4],  *c1b =(const float*)d_in[5];
    const float* gn2w=(const float*)d_in[6],  *gn2b=(const float*)d_in[7];
    const float* c2w =(const float*)d_in[8],  *c2b =(const float*)d_in[9];
    const float* clsw=(const float*)d_in[10], *clsb=(const float*)d_in[11];
    const float* mw1 =(const float*)d_in[12], *mb1 =(const float*)d_in[13];
    const float* mw2 =(const float*)d_in[14], *mb2 =(const float*)d_in[15];
    const float* mw3 =(const float*)d_in[16], *mb3 =(const float*)d_in[17];
    float* out=(float*)d_out;

    cudaFuncSetAttribute(main_kernel, cudaFuncAttributeMaxDynamicSharedMemorySize, SMEM_TOTAL);

    dim3 tgrid(HW/32, CH/32, BS), tblk(32,8);
    transpose_kernel<<<tgrid,tblk>>>(gimage);
    prep_kernel<<<384,256>>>(c1w,c2w,mw1,mw2);
    main_kernel<<<NBLK,256,SMEM_TOTAL>>>(pts,gn1w,gn1b,c1b,gn2w,gn2b,c2b,
                                         clsw,clsb,mb1,mb2,mw3,mb3,out);
}

// round 8
// speedup vs baseline: 2.6535x; 1.1988x over previous
#include <cuda_runtime.h>
#include <cuda_fp16.h>
#include <stdint.h>

#define HW 1024
#define CH 256
#define BS 32
#define NROWS 65536
#define MT 64
#define NBLK (NROWS/MT)

#define OFF_X   0                 // fp32 [64][264]
#define OFF_A   67584             // fp16 [64][264]
#define OFF_B   101376            // 2 x 32KB weight chunks
#define OFF_RED 166912
#define OFF_W3  171008
#define OFF_CW  175104
#define OFF_LIN 177152
#define SMEM_TOTAL 177664

__device__ float g_t[(size_t)BS*HW*CH];                       // [b][p][c]
__device__ __align__(16) unsigned char g_wb[(size_t)6*4*32768]; // frag-packed fp16 weights

// ---------- helpers ----------
__device__ __forceinline__ uint32_t s2u(const void* p){
    uint32_t a; asm("{ .reg .u64 t; cvta.to.shared.u64 t, %1; cvt.u32.u64 %0, t; }":"=r"(a):"l"(p)); return a;
}
__device__ __forceinline__ void cp16(uint32_t sdst, const void* g){
    asm volatile("cp.async.cg.shared.global [%0], [%1], 16;"::"r"(sdst),"l"(g));
}
__device__ __forceinline__ uint32_t lds32(uint32_t a){
    uint32_t v; asm volatile("ld.shared.b32 %0,[%1];":"=r"(v):"r"(a)); return v;
}
__device__ __forceinline__ void lds64(uint32_t a,uint32_t&x,uint32_t&y){
    asm volatile("ld.shared.v2.b32 {%0,%1},[%2];":"=r"(x),"=r"(y):"r"(a));
}
__device__ __forceinline__ void sts32(uint32_t a,uint32_t v){
    asm volatile("st.shared.b32 [%0],%1;"::"r"(a),"r"(v));
}
__device__ __forceinline__ void lds2f(uint32_t a,float&x,float&y){
    asm volatile("ld.shared.v2.f32 {%0,%1},[%2];":"=f"(x),"=f"(y):"r"(a));
}
__device__ __forceinline__ void sts2f(uint32_t a,float x,float y){
    asm volatile("st.shared.v2.f32 [%0],{%1,%2};"::"r"(a),"f"(x),"f"(y));
}
__device__ __forceinline__ float silu(float x){ return x/(1.f+__expf(-x)); }
__device__ __forceinline__ uint32_t packh2(float f0,float f1){
    __half2 h=__floats2half2_rn(f0,f1); return *(uint32_t*)&h;
}
__device__ __forceinline__ void mma16816(float* d,const uint32_t* a,uint32_t b0,uint32_t b1){
    asm volatile("mma.sync.aligned.m16n8k16.row.col.f32.f16.f16.f32 "
        "{%0,%1,%2,%3}, {%4,%5,%6,%7}, {%8,%9}, {%0,%1,%2,%3};"
        : "+f"(d[0]),"+f"(d[1]),"+f"(d[2]),"+f"(d[3])
        : "r"(a[0]),"r"(a[1]),"r"(a[2]),"r"(a[3]),"r"(b0),"r"(b1));
}
// GN over 8 channels spread across the 4 quad lanes (2 per lane)
#define GNPAIR(D0,D1,GW,GB,N0) { \
    float s_=(D0)+(D1); s_+=__shfl_xor_sync(0xffffffffu,s_,1); s_+=__shfl_xor_sync(0xffffffffu,s_,2); \
    float mn_=s_*0.125f, e0_=(D0)-mn_, e1_=(D1)-mn_; \
    float vv_=e0_*e0_+e1_*e1_; vv_+=__shfl_xor_sync(0xffffffffu,vv_,1); vv_+=__shfl_xor_sync(0xffffffffu,vv_,2); \
    float rs_=rsqrtf(vv_*0.125f+1e-5f); \
    (D0)=silu(e0_*rs_*(GW)[N0]+(GB)[N0]); (D1)=silu(e1_*rs_*(GW)[(N0)+1]+(GB)[(N0)+1]); }

// ---------- kernel 1: transpose [b][c][p] -> [b][p][c] ----------
__global__ void transpose_kernel(const float* __restrict__ g){
    __shared__ float tile[32][33];
    int b=blockIdx.z, p0=blockIdx.x*32, c0=blockIdx.y*32;
    int tx=threadIdx.x, ty=threadIdx.y;
    const float* src=g+(size_t)b*CH*HW;
    float* dst=g_t+(size_t)b*HW*CH;
#pragma unroll
    for(int i=0;i<4;i++) tile[ty+i*8][tx]=src[(size_t)(c0+ty+i*8)*HW+p0+tx];
    __syncthreads();
#pragma unroll
    for(int i=0;i<4;i++) dst[(size_t)(p0+ty+i*8)*CH+c0+tx]=tile[tx][ty+i*8];
}

// ---------- kernel 2: weights -> single-fp16 fragment-packed 32KB chunks -----
// chunk (w,kc): 64 k-values; frag (ks,nt): 32 lanes x uint2
__global__ void prep_kernel(const float* __restrict__ c1,const float* __restrict__ c2,
                            const float* __restrict__ m1,const float* __restrict__ m2){
    int gid=blockIdx.x*256+threadIdx.x;          // 98304 total
    int lane=gid&31, nt=(gid>>5)&31, ks=(gid>>10)&3, kc=(gid>>12)&3, w=gid>>14;
    int q=lane&3, g=lane>>2;
    int n=nt*8+g;
    int k0=kc*64+ks*16+q*2;
    float v0,v1,v2,v3;
    if(w<4){
        const float* s=(w&1)?c2:c1; int L=w>>1;
        const float* p=s+((size_t)(L*CH+n)*CH)*9+4;
        v0=p[(size_t)k0*9]; v1=p[(size_t)(k0+1)*9];
        v2=p[(size_t)(k0+8)*9]; v3=p[(size_t)(k0+9)*9];
    } else {
        const float* p=((w==4)?m1:m2)+(size_t)n*CH;
        v0=p[k0]; v1=p[k0+1]; v2=p[k0+8]; v3=p[k0+9];
    }
    size_t base=(size_t)(w*4+kc)*32768;
    uint32_t fo=((uint32_t)(ks*32+nt)*32+lane)*8;
    *(uint2*)(g_wb+base+fo)=make_uint2(packh2(v0,v1),packh2(v2,v3));
}

// ---------- GEMM: D[64][256] = A[64][256] x W^T, single-pass fp16 ----------
__device__ __forceinline__ void run_gemm(int w,uint32_t smb,int tid,
                                         int mq,int nh,int g,int q,float d[16][4]){
#pragma unroll
    for(int i=0;i<16;i++){d[i][0]=0.f;d[i][1]=0.f;d[i][2]=0.f;d[i][3]=0.f;}
    {   const unsigned char* src=g_wb+(size_t)(w*4)*32768;
        uint32_t dst=smb+OFF_B;
#pragma unroll
        for(int j=0;j<8;j++) cp16(dst+j*4096+tid*16, src+j*4096+tid*16);
        asm volatile("cp.async.commit_group;");
    }
    uint32_t aH=smb+OFF_A+(mq*16+g)*528;
#pragma unroll 1
    for(int kc=0;kc<4;kc++){
        if(kc<3){
            const unsigned char* src=g_wb+(size_t)(w*4+kc+1)*32768;
            uint32_t dst=smb+OFF_B+((kc+1)&1)*32768;
#pragma unroll
            for(int j=0;j<8;j++) cp16(dst+j*4096+tid*16, src+j*4096+tid*16);
            asm volatile("cp.async.commit_group;");
            asm volatile("cp.async.wait_group 1;");
        } else asm volatile("cp.async.wait_group 0;");
        __syncthreads();
        uint32_t bb=smb+OFF_B+(kc&1)*32768;
#pragma unroll
        for(int ks=0;ks<4;ks++){
            int koff=(kc*64+ks*16+q*2)*2;
            uint32_t ah[4];
            ah[0]=lds32(aH+koff);       ah[1]=lds32(aH+koff+8*528);
            ah[2]=lds32(aH+koff+16);    ah[3]=lds32(aH+koff+8*528+16);
            uint32_t fb=bb+((uint32_t)(ks*32+nh*16)*32+(tid&31))*8;
#pragma unroll
            for(int i=0;i<16;i++){
                uint32_t b0,b1;
                lds64(fb+i*256,b0,b1);
                mma16816(d[i],ah,b0,b1);
            }
        }
        __syncthreads();
    }
}

// ---------- fused main kernel ----------
__global__ __launch_bounds__(256,1) void main_kernel(
    const int* __restrict__ pts,
    const float* __restrict__ gn1w,const float* __restrict__ gn1b,
    const float* __restrict__ c1b,
    const float* __restrict__ gn2w,const float* __restrict__ gn2b,
    const float* __restrict__ c2b,
    const float* __restrict__ clsw,const float* __restrict__ clsb,
    const float* __restrict__ mb1,const float* __restrict__ mb2,
    const float* __restrict__ mw3,const float* __restrict__ mb3,
    float* __restrict__ out)
{
    extern __shared__ __align__(16) unsigned char smp[];
    uint32_t smb=s2u(smp);
    int tid=threadIdx.x, lane=tid&31, wid=tid>>5;
    int mq=wid&3, nh=wid>>2, g=lane>>2, q=lane&3;
    int row_base=blockIdx.x*MT;
    float* w3s=(float*)(smp+OFF_W3);
    float* cws=(float*)(smp+OFF_CW);
    float* red=(float*)(smp+OFF_RED);

    for(int i=tid;i<1024;i+=256) w3s[i]=mw3[i];
    for(int i=tid;i<512;i+=256)  cws[i]=clsw[i];
    if(tid<MT){
        int r=row_base+tid;
        int p0=pts[r*2], p1=pts[r*2+1];
        ((int*)(smp+OFF_LIN))[tid]=((r>>11)*HW+((p0>>3)*32+(p1>>3)))*CH;
    }
    __syncthreads();

    // gather -> xs(f32) ; GN1[0]+SiLU -> A(fp16)
    {
        int row=tid>>2, t4=tid&3;
        const float* src=g_t+((const int*)(smp+OFF_LIN))[row]+t4*64;
        float v[64];
#pragma unroll
        for(int i=0;i<16;i++) *(float4*)(v+i*4)=*(const float4*)(src+i*4);
        uint32_t xb=smb+OFF_X+row*1056+t4*256;
#pragma unroll
        for(int i=0;i<16;i++)
            asm volatile("st.shared.v4.f32 [%0],{%1,%2,%3,%4};"
                ::"r"(xb+i*16),"f"(v[i*4]),"f"(v[i*4+1]),"f"(v[i*4+2]),"f"(v[i*4+3]));
#pragma unroll
        for(int gr=0;gr<8;gr++){
            float s=0.f,vv=0.f;
#pragma unroll
            for(int j=0;j<8;j++) s+=v[gr*8+j];
            float mean=s*0.125f;
#pragma unroll
            for(int j=0;j<8;j++){float e=v[gr*8+j]-mean; vv+=e*e;}
            float rs=rsqrtf(vv*0.125f+1e-5f);
#pragma unroll
            for(int j=0;j<8;j++){
                int n=t4*64+gr*8+j;
                v[gr*8+j]=silu((v[gr*8+j]-mean)*rs*gn1w[n]+gn1b[n]);
            }
        }
        uint32_t ahb=smb+OFF_A+row*528+t4*128;
#pragma unroll
        for(int j2=0;j2<32;j2++) sts32(ahb+j2*4,packh2(v[2*j2],v[2*j2+1]));
    }
    __syncthreads();

    float d[16][4];
    int mg=mq*16+g;
    uint32_t ah_w=smb+OFF_A+mg*528;
    uint32_t xs_w=smb+OFF_X+mg*1056;

#pragma unroll 1
    for(int L=0;L<2;++L){
        run_gemm(L*2+0,smb,tid,mq,nh,g,q,d);               // conv1
        const float* b1=c1b+L*CH; const float* g2w=gn2w+L*CH; const float* g2b=gn2b+L*CH;
#pragma unroll
        for(int i=0;i<16;i++){
            int n0=(nh*16+i)*8+q*2;
            d[i][0]+=b1[n0]; d[i][1]+=b1[n0+1]; d[i][2]+=b1[n0]; d[i][3]+=b1[n0+1];
            GNPAIR(d[i][0],d[i][1],g2w,g2b,n0);
            GNPAIR(d[i][2],d[i][3],g2w,g2b,n0);
            sts32(ah_w+n0*2,packh2(d[i][0],d[i][1]));
            sts32(ah_w+8*528+n0*2,packh2(d[i][2],d[i][3]));
        }
        __syncthreads();

        run_gemm(L*2+1,smb,tid,mq,nh,g,q,d);               // conv2
        const float* b2=c2b+L*CH; const float* g1w=gn1w+CH; const float* g1b=gn1b+CH;
#pragma unroll
        for(int i=0;i<16;i++){
            int n0=(nh*16+i)*8+q*2;
            float x0,x1;
            lds2f(xs_w+n0*4,x0,x1);
            d[i][0]+=b2[n0]+x0; d[i][1]+=b2[n0+1]+x1;
            sts2f(xs_w+n0*4,d[i][0],d[i][1]);
            lds2f(xs_w+8*1056+n0*4,x0,x1);
            d[i][2]+=b2[n0]+x0; d[i][3]+=b2[n0+1]+x1;
            sts2f(xs_w+8*1056+n0*4,d[i][2],d[i][3]);
            if(L==0){ GNPAIR(d[i][0],d[i][1],g1w,g1b,n0); GNPAIR(d[i][2],d[i][3],g1w,g1b,n0); }
            sts32(ah_w+n0*2,packh2(d[i][0],d[i][1]));
            sts32(ah_w+8*528+n0*2,packh2(d[i][2],d[i][3]));
        }
        __syncthreads();
    }

    run_gemm(4,smb,tid,mq,nh,g,q,d);                       // mlp1
#pragma unroll
    for(int i=0;i<16;i++){
        int n0=(nh*16+i)*8+q*2;
        d[i][0]=fmaxf(d[i][0]+mb1[n0],0.f);   d[i][1]=fmaxf(d[i][1]+mb1[n0+1],0.f);
        d[i][2]=fmaxf(d[i][2]+mb1[n0],0.f);   d[i][3]=fmaxf(d[i][3]+mb1[n0+1],0.f);
        sts32(ah_w+n0*2,packh2(d[i][0],d[i][1]));
        sts32(ah_w+8*528+n0*2,packh2(d[i][2],d[i][3]));
    }
    __syncthreads();

    run_gemm(5,smb,tid,mq,nh,g,q,d);                       // mlp2
    {
        float bg[4]={0,0,0,0}, bh[4]={0,0,0,0};
#pragma unroll
        for(int i=0;i<16;i++){
            int n0=(nh*16+i)*8+q*2;
            float t0=fmaxf(d[i][0]+mb2[n0],0.f),  t1=fmaxf(d[i][1]+mb2[n0+1],0.f);
            float t2=fmaxf(d[i][2]+mb2[n0],0.f),  t3=fmaxf(d[i][3]+mb2[n0+1],0.f);
#pragma unroll
            for(int s=0;s<4;s++){
                float w0=w3s[s*256+n0], w1=w3s[s*256+n0+1];
                bg[s]+=t0*w0+t1*w1;
                bh[s]+=t2*w0+t3*w1;
            }
        }
#pragma unroll
        for(int s=0;s<4;s++){
            bg[s]+=__shfl_xor_sync(0xffffffffu,bg[s],1); bg[s]+=__shfl_xor_sync(0xffffffffu,bg[s],2);
            bh[s]+=__shfl_xor_sync(0xffffffffu,bh[s],1); bh[s]+=__shfl_xor_sync(0xffffffffu,bh[s],2);
        }
        if(q==0){
#pragma unroll
            for(int s=0;s<4;s++){
                red[mg*16+nh*8+s]=bg[s];
                red[(mg+8)*16+nh*8+s]=bh[s];
            }
        }
    }
    __syncthreads();

    // heads out
    if(tid<MT){
        size_t row=(size_t)row_base+tid;
#pragma unroll
        for(int s=0;s<4;s++){
            float a=red[tid*16+s]+red[tid*16+8+s]+mb3[s];
            out[131072+row*4+s]=1.f/(1.f+__expf(-a));
        }
    }
    {
        int row=tid>>2, t4=tid&3;
        float c0=0.f,c1=0.f;
#pragma unroll 16
        for(int i=0;i<64;i++){
            int k=t4+4*i;
            float xv=*(float*)(smp+OFF_X+row*1056+k*4);
            c0+=xv*cws[k]; c1+=xv*cws[256+k];
        }
        c0+=__shfl_xor_sync(0xffffffffu,c0,1); c0+=__shfl_xor_sync(0xffffffffu,c0,2);
        c1+=__shfl_xor_sync(0xffffffffu,c1,1); c1+=__shfl_xor_sync(0xffffffffu,c1,2);
        if(t4==0){
            size_t r=(size_t)row_base+row;
            out[r*2+0]=c0+clsb[0];
            out[r*2+1]=c1+clsb[1];
        }
    }
}

// ---------- launch ----------
extern "C" void kernel_launch(void* const* d_in, const int* in_sizes, int n_in,
                              void* d_out, int out_size){
    const float* gimage=(const float*)d_in[0];
    const int*   pts   =(const int*)  d_in[1];
    const float* gn1w=(const float*)d_in[2],  *gn1b=(const float*)d_in[3];
    const float* c1w =(const float*)d_in[4],  *c1b =(const float*)d_in[5];
    const float* gn2w=(const float*)d_in[6],  *gn2b=(const float*)d_in[7];
    const float* c2w =(const float*)d_in[8],  *c2b =(const float*)d_in[9];
    const float* clsw=(const float*)d_in[10], *clsb=(const float*)d_in[11];
    const float* mw1 =(const float*)d_in[12], *mb1 =(const float*)d_in[13];
    const float* mw2 =(const float*)d_in[14], *mb2 =(const float*)d_in[15];
    const float* mw3 =(const float*)d_in[16], *mb3 =(const float*)d_in[17];
    float* out=(float*)d_out;

    cudaFuncSetAttribute(main_kernel, cudaFuncAttributeMaxDynamicSharedMemorySize, SMEM_TOTAL);

    dim3 tgrid(HW/32, CH/32, BS), tblk(32,8);
    transpose_kernel<<<tgrid,tblk>>>(gimage);
    prep_kernel<<<384,256>>>(c1w,c2w,mw1,mw2);
    main_kernel<<<NBLK,256,SMEM_TOTAL>>>(pts,gn1w,gn1b,c1b,gn2w,gn2b,c2b,
                                         clsw,clsb,mb1,mb2,mw3,mb3,out);
}

// round 9
// speedup vs baseline: 3.5330x; 1.3314x over previous
#include <cuda_runtime.h>
#include <cuda_fp16.h>
#include <stdint.h>

#define HW 1024
#define CH 256
#define BS 32
#define NROWS 65536
#define MT 32
#define NBLK (NROWS/MT)

#define OFF_X   0                 // fp32 [32][264]
#define OFF_A   33792             // fp16 [32][264]
#define OFF_B   50688             // 2 x 16KB weight chunks
#define OFF_RED 83456
#define OFF_W3  85504
#define OFF_CW  89600
#define OFF_LIN 91648
#define SMEM_TOTAL 91776

__device__ float g_t[(size_t)BS*HW*CH];                       // [b][p][c]
__device__ __align__(16) unsigned char g_wb[(size_t)6*8*16384]; // frag-packed fp16 weights

// ---------- helpers ----------
__device__ __forceinline__ uint32_t s2u(const void* p){
    uint32_t a; asm("{ .reg .u64 t; cvta.to.shared.u64 t, %1; cvt.u32.u64 %0, t; }":"=r"(a):"l"(p)); return a;
}
__device__ __forceinline__ void cp16(uint32_t sdst, const void* g){
    asm volatile("cp.async.cg.shared.global [%0], [%1], 16;"::"r"(sdst),"l"(g));
}
__device__ __forceinline__ uint32_t lds32(uint32_t a){
    uint32_t v; asm volatile("ld.shared.b32 %0,[%1];":"=r"(v):"r"(a)); return v;
}
__device__ __forceinline__ void lds64(uint32_t a,uint32_t&x,uint32_t&y){
    asm volatile("ld.shared.v2.b32 {%0,%1},[%2];":"=r"(x),"=r"(y):"r"(a));
}
__device__ __forceinline__ void sts32(uint32_t a,uint32_t v){
    asm volatile("st.shared.b32 [%0],%1;"::"r"(a),"r"(v));
}
__device__ __forceinline__ void lds2f(uint32_t a,float&x,float&y){
    asm volatile("ld.shared.v2.f32 {%0,%1},[%2];":"=f"(x),"=f"(y):"r"(a));
}
__device__ __forceinline__ void sts2f(uint32_t a,float x,float y){
    asm volatile("st.shared.v2.f32 [%0],{%1,%2};"::"r"(a),"f"(x),"f"(y));
}
__device__ __forceinline__ float silu(float x){ return x/(1.f+__expf(-x)); }
__device__ __forceinline__ uint32_t packh2(float f0,float f1){
    __half2 h=__floats2half2_rn(f0,f1); return *(uint32_t*)&h;
}
__device__ __forceinline__ void mma16816(float* d,const uint32_t* a,uint32_t b0,uint32_t b1){
    asm volatile("mma.sync.aligned.m16n8k16.row.col.f32.f16.f16.f32 "
        "{%0,%1,%2,%3}, {%4,%5,%6,%7}, {%8,%9}, {%0,%1,%2,%3};"
        : "+f"(d[0]),"+f"(d[1]),"+f"(d[2]),"+f"(d[3])
        : "r"(a[0]),"r"(a[1]),"r"(a[2]),"r"(a[3]),"r"(b0),"r"(b1));
}
// GN over 8 channels spread across the 4 quad lanes (2 per lane)
#define GNPAIR(D0,D1,GW,GB,N0) { \
    float s_=(D0)+(D1); s_+=__shfl_xor_sync(0xffffffffu,s_,1); s_+=__shfl_xor_sync(0xffffffffu,s_,2); \
    float mn_=s_*0.125f, e0_=(D0)-mn_, e1_=(D1)-mn_; \
    float vv_=e0_*e0_+e1_*e1_; vv_+=__shfl_xor_sync(0xffffffffu,vv_,1); vv_+=__shfl_xor_sync(0xffffffffu,vv_,2); \
    float rs_=rsqrtf(vv_*0.125f+1e-5f); \
    (D0)=silu(e0_*rs_*(GW)[N0]+(GB)[N0]); (D1)=silu(e1_*rs_*(GW)[(N0)+1]+(GB)[(N0)+1]); }

// ---------- kernel 1: transpose [b][c][p] -> [b][p][c] ----------
__global__ void transpose_kernel(const float* __restrict__ g){
    __shared__ float tile[32][33];
    int b=blockIdx.z, p0=blockIdx.x*32, c0=blockIdx.y*32;
    int tx=threadIdx.x, ty=threadIdx.y;
    const float* src=g+(size_t)b*CH*HW;
    float* dst=g_t+(size_t)b*HW*CH;
#pragma unroll
    for(int i=0;i<4;i++) tile[ty+i*8][tx]=src[(size_t)(c0+ty+i*8)*HW+p0+tx];
    __syncthreads();
#pragma unroll
    for(int i=0;i<4;i++) dst[(size_t)(p0+ty+i*8)*CH+c0+tx]=tile[tx][ty+i*8];
}

// ---------- kernel 2: weights -> fp16 fragment-packed 16KB chunks ----------
// chunk (w,kc): 32 k-values; frag (ks,nt): 32 lanes x uint2
__global__ void prep_kernel(const float* __restrict__ c1,const float* __restrict__ c2,
                            const float* __restrict__ m1,const float* __restrict__ m2){
    int gid=blockIdx.x*256+threadIdx.x;          // 98304 total
    int lane=gid&31, nt=(gid>>5)&31, ks=(gid>>10)&1, kc=(gid>>11)&7, w=gid>>14;
    int q=lane&3, g=lane>>2;
    int n=nt*8+g;
    int k0=kc*32+ks*16+q*2;
    float v0,v1,v2,v3;
    if(w<4){
        const float* s=(w&1)?c2:c1; int L=w>>1;
        const float* p=s+((size_t)(L*CH+n)*CH)*9+4;
        v0=p[(size_t)k0*9]; v1=p[(size_t)(k0+1)*9];
        v2=p[(size_t)(k0+8)*9]; v3=p[(size_t)(k0+9)*9];
    } else {
        const float* p=((w==4)?m1:m2)+(size_t)n*CH;
        v0=p[k0]; v1=p[k0+1]; v2=p[k0+8]; v3=p[k0+9];
    }
    size_t base=(size_t)(w*8+kc)*16384;
    uint32_t fo=((uint32_t)(ks*32+nt)*32+lane)*8;
    *(uint2*)(g_wb+base+fo)=make_uint2(packh2(v0,v1),packh2(v2,v3));
}

// ---------- GEMM: D[32][256] = A[32][256] x W^T, single-pass fp16 ----------
__device__ __forceinline__ void run_gemm(int w,uint32_t smb,int tid,
                                         int mq,int nh,int g,int q,float d[8][4]){
#pragma unroll
    for(int i=0;i<8;i++){d[i][0]=0.f;d[i][1]=0.f;d[i][2]=0.f;d[i][3]=0.f;}
    {   const unsigned char* src=g_wb+(size_t)(w*8)*16384;
        uint32_t dst=smb+OFF_B;
#pragma unroll
        for(int j=0;j<4;j++) cp16(dst+j*4096+tid*16, src+j*4096+tid*16);
        asm volatile("cp.async.commit_group;");
    }
    uint32_t aH=smb+OFF_A+(mq*16+g)*528;
#pragma unroll 1
    for(int kc=0;kc<8;kc++){
        if(kc<7){
            const unsigned char* src=g_wb+(size_t)(w*8+kc+1)*16384;
            uint32_t dst=smb+OFF_B+((kc+1)&1)*16384;
#pragma unroll
            for(int j=0;j<4;j++) cp16(dst+j*4096+tid*16, src+j*4096+tid*16);
            asm volatile("cp.async.commit_group;");
            asm volatile("cp.async.wait_group 1;");
        } else asm volatile("cp.async.wait_group 0;");
        __syncthreads();
        uint32_t bb=smb+OFF_B+(kc&1)*16384;
#pragma unroll
        for(int ks=0;ks<2;ks++){
            int koff=(kc*32+ks*16+q*2)*2;
            uint32_t ah[4];
            ah[0]=lds32(aH+koff);       ah[1]=lds32(aH+koff+8*528);
            ah[2]=lds32(aH+koff+16);    ah[3]=lds32(aH+koff+8*528+16);
            uint32_t fb=bb+((uint32_t)(ks*32+nh*8)*32+(tid&31))*8;
#pragma unroll
            for(int i=0;i<8;i++){
                uint32_t b0,b1;
                lds64(fb+i*256,b0,b1);
                mma16816(d[i],ah,b0,b1);
            }
        }
        __syncthreads();
    }
}

// ---------- fused main kernel ----------
__global__ __launch_bounds__(256,2) void main_kernel(
    const int* __restrict__ pts,
    const float* __restrict__ gn1w,const float* __restrict__ gn1b,
    const float* __restrict__ c1b,
    const float* __restrict__ gn2w,const float* __restrict__ gn2b,
    const float* __restrict__ c2b,
    const float* __restrict__ clsw,const float* __restrict__ clsb,
    const float* __restrict__ mb1,const float* __restrict__ mb2,
    const float* __restrict__ mw3,const float* __restrict__ mb3,
    float* __restrict__ out)
{
    extern __shared__ __align__(16) unsigned char smp[];
    uint32_t smb=s2u(smp);
    int tid=threadIdx.x, lane=tid&31, wid=tid>>5;
    int mq=wid&1, nh=wid>>1, g=lane>>2, q=lane&3;
    int row_base=blockIdx.x*MT;
    float* w3s=(float*)(smp+OFF_W3);
    float* cws=(float*)(smp+OFF_CW);
    float* red=(float*)(smp+OFF_RED);

    for(int i=tid;i<1024;i+=256) w3s[i]=mw3[i];
    for(int i=tid;i<512;i+=256)  cws[i]=clsw[i];
    if(tid<MT){
        int r=row_base+tid;
        int p0=pts[r*2], p1=pts[r*2+1];
        ((int*)(smp+OFF_LIN))[tid]=((r>>11)*HW+((p0>>3)*32+(p1>>3)))*CH;
    }
    __syncthreads();

    // gather -> xs(f32) ; GN1[0]+SiLU -> A(fp16)
    {
        int row=tid>>3, t8=tid&7;
        const float* src=g_t+((const int*)(smp+OFF_LIN))[row]+t8*32;
        float v[32];
#pragma unroll
        for(int i=0;i<8;i++) *(float4*)(v+i*4)=*(const float4*)(src+i*4);
        uint32_t xb=smb+OFF_X+row*1056+t8*128;
#pragma unroll
        for(int i=0;i<8;i++)
            asm volatile("st.shared.v4.f32 [%0],{%1,%2,%3,%4};"
                ::"r"(xb+i*16),"f"(v[i*4]),"f"(v[i*4+1]),"f"(v[i*4+2]),"f"(v[i*4+3]));
#pragma unroll
        for(int gr=0;gr<4;gr++){
            float s=0.f,vv=0.f;
#pragma unroll
            for(int j=0;j<8;j++) s+=v[gr*8+j];
            float mean=s*0.125f;
#pragma unroll
            for(int j=0;j<8;j++){float e=v[gr*8+j]-mean; vv+=e*e;}
            float rs=rsqrtf(vv*0.125f+1e-5f);
#pragma unroll
            for(int j=0;j<8;j++){
                int n=t8*32+gr*8+j;
                v[gr*8+j]=silu((v[gr*8+j]-mean)*rs*gn1w[n]+gn1b[n]);
            }
        }
        uint32_t ahb=smb+OFF_A+row*528+t8*64;
#pragma unroll
        for(int j2=0;j2<16;j2++) sts32(ahb+j2*4,packh2(v[2*j2],v[2*j2+1]));
    }
    __syncthreads();

    float d[8][4];
    int mg=mq*16+g;
    uint32_t ah_w=smb+OFF_A+mg*528;
    uint32_t xs_w=smb+OFF_X+mg*1056;

#pragma unroll 1
    for(int L=0;L<2;++L){
        run_gemm(L*2+0,smb,tid,mq,nh,g,q,d);               // conv1
        const float* b1=c1b+L*CH; const float* g2w=gn2w+L*CH; const float* g2b=gn2b+L*CH;
#pragma unroll
        for(int i=0;i<8;i++){
            int n0=(nh*8+i)*8+q*2;
            d[i][0]+=b1[n0]; d[i][1]+=b1[n0+1]; d[i][2]+=b1[n0]; d[i][3]+=b1[n0+1];
            GNPAIR(d[i][0],d[i][1],g2w,g2b,n0);
            GNPAIR(d[i][2],d[i][3],g2w,g2b,n0);
            sts32(ah_w+n0*2,packh2(d[i][0],d[i][1]));
            sts32(ah_w+8*528+n0*2,packh2(d[i][2],d[i][3]));
        }
        __syncthreads();

        run_gemm(L*2+1,smb,tid,mq,nh,g,q,d);               // conv2
        const float* b2=c2b+L*CH; const float* g1w=gn1w+CH; const float* g1b=gn1b+CH;
#pragma unroll
        for(int i=0;i<8;i++){
            int n0=(nh*8+i)*8+q*2;
            float x0,x1;
            lds2f(xs_w+n0*4,x0,x1);
            d[i][0]+=b2[n0]+x0; d[i][1]+=b2[n0+1]+x1;
            sts2f(xs_w+n0*4,d[i][0],d[i][1]);
            lds2f(xs_w+8*1056+n0*4,x0,x1);
            d[i][2]+=b2[n0]+x0; d[i][3]+=b2[n0+1]+x1;
            sts2f(xs_w+8*1056+n0*4,d[i][2],d[i][3]);
            if(L==0){ GNPAIR(d[i][0],d[i][1],g1w,g1b,n0); GNPAIR(d[i][2],d[i][3],g1w,g1b,n0); }
            sts32(ah_w+n0*2,packh2(d[i][0],d[i][1]));
            sts32(ah_w+8*528+n0*2,packh2(d[i][2],d[i][3]));
        }
        __syncthreads();
    }

    run_gemm(4,smb,tid,mq,nh,g,q,d);                       // mlp1
#pragma unroll
    for(int i=0;i<8;i++){
        int n0=(nh*8+i)*8+q*2;
        d[i][0]=fmaxf(d[i][0]+mb1[n0],0.f);   d[i][1]=fmaxf(d[i][1]+mb1[n0+1],0.f);
        d[i][2]=fmaxf(d[i][2]+mb1[n0],0.f);   d[i][3]=fmaxf(d[i][3]+mb1[n0+1],0.f);
        sts32(ah_w+n0*2,packh2(d[i][0],d[i][1]));
        sts32(ah_w+8*528+n0*2,packh2(d[i][2],d[i][3]));
    }
    __syncthreads();

    run_gemm(5,smb,tid,mq,nh,g,q,d);                       // mlp2
    {
        float bg[4]={0,0,0,0}, bh[4]={0,0,0,0};
#pragma unroll
        for(int i=0;i<8;i++){
            int n0=(nh*8+i)*8+q*2;
            float t0=fmaxf(d[i][0]+mb2[n0],0.f),  t1=fmaxf(d[i][1]+mb2[n0+1],0.f);
            float t2=fmaxf(d[i][2]+mb2[n0],0.f),  t3=fmaxf(d[i][3]+mb2[n0+1],0.f);
#pragma unroll
            for(int s=0;s<4;s++){
                float w0=w3s[s*256+n0], w1=w3s[s*256+n0+1];
                bg[s]+=t0*w0+t1*w1;
                bh[s]+=t2*w0+t3*w1;
            }
        }
#pragma unroll
        for(int s=0;s<4;s++){
            bg[s]+=__shfl_xor_sync(0xffffffffu,bg[s],1); bg[s]+=__shfl_xor_sync(0xffffffffu,bg[s],2);
            bh[s]+=__shfl_xor_sync(0xffffffffu,bh[s],1); bh[s]+=__shfl_xor_sync(0xffffffffu,bh[s],2);
        }
        if(q==0){
#pragma unroll
            for(int s=0;s<4;s++){
                red[mg*16+nh*4+s]=bg[s];
                red[(mg+8)*16+nh*4+s]=bh[s];
            }
        }
    }
    __syncthreads();

    // heads out
    if(tid<MT){
        size_t row=(size_t)row_base+tid;
#pragma unroll
        for(int s=0;s<4;s++){
            float a=red[tid*16+s]+red[tid*16+4+s]+red[tid*16+8+s]+red[tid*16+12+s]+mb3[s];
            out[131072+row*4+s]=1.f/(1.f+__expf(-a));
        }
    }
    {
        int row=tid>>3, t8=tid&7;
        float c0=0.f,c1=0.f;
#pragma unroll 8
        for(int i=0;i<32;i++){
            int k=t8+8*i;
            float xv=*(float*)(smp+OFF_X+row*1056+k*4);
            c0+=xv*cws[k]; c1+=xv*cws[256+k];
        }
        c0+=__shfl_xor_sync(0xffffffffu,c0,1); c0+=__shfl_xor_sync(0xffffffffu,c0,2); c0+=__shfl_xor_sync(0xffffffffu,c0,4);
        c1+=__shfl_xor_sync(0xffffffffu,c1,1); c1+=__shfl_xor_sync(0xffffffffu,c1,2); c1+=__shfl_xor_sync(0xffffffffu,c1,4);
        if(t8==0){
            size_t r=(size_t)row_base+row;
            out[r*2+0]=c0+clsb[0];
            out[r*2+1]=c1+clsb[1];
        }
    }
}

// ---------- launch ----------
extern "C" void kernel_launch(void* const* d_in, const int* in_sizes, int n_in,
                              void* d_out, int out_size){
    const float* gimage=(const float*)d_in[0];
    const int*   pts   =(const int*)  d_in[1];
    const float* gn1w=(const float*)d_in[2],  *gn1b=(const float*)d_in[3];
    const float* c1w =(const float*)d_in[4],  *c1b =(const float*)d_in[5];
    const float* gn2w=(const float*)d_in[6],  *gn2b=(const float*)d_in[7];
    const float* c2w =(const float*)d_in[8],  *c2b =(const float*)d_in[9];
    const float* clsw=(const float*)d_in[10], *clsb=(const float*)d_in[11];
    const float* mw1 =(const float*)d_in[12], *mb1 =(const float*)d_in[13];
    const float* mw2 =(const float*)d_in[14], *mb2 =(const float*)d_in[15];
    const float* mw3 =(const float*)d_in[16], *mb3 =(const float*)d_in[17];
    float* out=(float*)d_out;

    cudaFuncSetAttribute(main_kernel, cudaFuncAttributeMaxDynamicSharedMemorySize, SMEM_TOTAL);

    dim3 tgrid(HW/32, CH/32, BS), tblk(32,8);
    transpose_kernel<<<tgrid,tblk>>>(gimage);
    prep_kernel<<<384,256>>>(c1w,c2w,mw1,mw2);
    main_kernel<<<NBLK,256,SMEM_TOTAL>>>(pts,gn1w,gn1b,c1b,gn2w,gn2b,c2b,
                                         clsw,clsb,mb1,mb2,mw3,mb3,out);
}

// round 10
// speedup vs baseline: 3.6118x; 1.0223x over previous
#include <cuda_runtime.h>
#include <cuda_fp16.h>
#include <stdint.h>

#define HW 1024
#define CH 256
#define BS 32
#define NROWS 65536
#define MT 64
#define NBLK (NROWS/MT)

#define OFF_X   0                 // fp16 [64][264]
#define OFF_A   33792             // fp16 [64][264]
#define OFF_B   67584             // 2 x 16KB weight chunks
#define OFF_RED 100352
#define OFF_W3  104448
#define OFF_CW  108544
#define OFF_LIN 110592
#define SMEM_TOTAL 110848

__device__ float g_t[(size_t)BS*HW*CH];                       // [b][p][c]
__device__ __align__(16) unsigned char g_wb[(size_t)6*8*16384]; // frag-packed fp16 weights

// ---------- helpers ----------
__device__ __forceinline__ uint32_t s2u(const void* p){
    uint32_t a; asm("{ .reg .u64 t; cvta.to.shared.u64 t, %1; cvt.u32.u64 %0, t; }":"=r"(a):"l"(p)); return a;
}
__device__ __forceinline__ void cp16(uint32_t sdst, const void* g){
    asm volatile("cp.async.cg.shared.global [%0], [%1], 16;"::"r"(sdst),"l"(g));
}
__device__ __forceinline__ uint32_t lds32(uint32_t a){
    uint32_t v; asm volatile("ld.shared.b32 %0,[%1];":"=r"(v):"r"(a)); return v;
}
__device__ __forceinline__ void lds64(uint32_t a,uint32_t&x,uint32_t&y){
    asm volatile("ld.shared.v2.b32 {%0,%1},[%2];":"=r"(x),"=r"(y):"r"(a));
}
__device__ __forceinline__ void sts32(uint32_t a,uint32_t v){
    asm volatile("st.shared.b32 [%0],%1;"::"r"(a),"r"(v));
}
__device__ __forceinline__ float silu(float x){ return x/(1.f+__expf(-x)); }
__device__ __forceinline__ uint32_t packh2(float f0,float f1){
    __half2 h=__floats2half2_rn(f0,f1); return *(uint32_t*)&h;
}
__device__ __forceinline__ float2 unph2(uint32_t u){
    return __half22float2(*(__half2*)&u);
}
__device__ __forceinline__ void mma16816(float* d,const uint32_t* a,uint32_t b0,uint32_t b1){
    asm volatile("mma.sync.aligned.m16n8k16.row.col.f32.f16.f16.f32 "
        "{%0,%1,%2,%3}, {%4,%5,%6,%7}, {%8,%9}, {%0,%1,%2,%3};"
        : "+f"(d[0]),"+f"(d[1]),"+f"(d[2]),"+f"(d[3])
        : "r"(a[0]),"r"(a[1]),"r"(a[2]),"r"(a[3]),"r"(b0),"r"(b1));
}
// GN over 8 channels spread across the 4 quad lanes (2 per lane)
#define GNPAIR(D0,D1,GW,GB,N0) { \
    float s_=(D0)+(D1); s_+=__shfl_xor_sync(0xffffffffu,s_,1); s_+=__shfl_xor_sync(0xffffffffu,s_,2); \
    float mn_=s_*0.125f, e0_=(D0)-mn_, e1_=(D1)-mn_; \
    float vv_=e0_*e0_+e1_*e1_; vv_+=__shfl_xor_sync(0xffffffffu,vv_,1); vv_+=__shfl_xor_sync(0xffffffffu,vv_,2); \
    float rs_=rsqrtf(vv_*0.125f+1e-5f); \
    (D0)=silu(e0_*rs_*(GW)[N0]+(GB)[N0]); (D1)=silu(e1_*rs_*(GW)[(N0)+1]+(GB)[(N0)+1]); }

// ---------- kernel 1: transpose [b][c][p] -> [b][p][c] ----------
__global__ void transpose_kernel(const float* __restrict__ g){
    __shared__ float tile[32][33];
    int b=blockIdx.z, p0=blockIdx.x*32, c0=blockIdx.y*32;
    int tx=threadIdx.x, ty=threadIdx.y;
    const float* src=g+(size_t)b*CH*HW;
    float* dst=g_t+(size_t)b*HW*CH;
#pragma unroll
    for(int i=0;i<4;i++) tile[ty+i*8][tx]=src[(size_t)(c0+ty+i*8)*HW+p0+tx];
    __syncthreads();
#pragma unroll
    for(int i=0;i<4;i++) dst[(size_t)(p0+ty+i*8)*CH+c0+tx]=tile[tx][ty+i*8];
}

// ---------- kernel 2: weights -> fp16 fragment-packed 16KB chunks ----------
__global__ void prep_kernel(const float* __restrict__ c1,const float* __restrict__ c2,
                            const float* __restrict__ m1,const float* __restrict__ m2){
    int gid=blockIdx.x*256+threadIdx.x;          // 98304 total
    int lane=gid&31, nt=(gid>>5)&31, ks=(gid>>10)&1, kc=(gid>>11)&7, w=gid>>14;
    int q=lane&3, g=lane>>2;
    int n=nt*8+g;
    int k0=kc*32+ks*16+q*2;
    float v0,v1,v2,v3;
    if(w<4){
        const float* s=(w&1)?c2:c1; int L=w>>1;
        const float* p=s+((size_t)(L*CH+n)*CH)*9+4;
        v0=p[(size_t)k0*9]; v1=p[(size_t)(k0+1)*9];
        v2=p[(size_t)(k0+8)*9]; v3=p[(size_t)(k0+9)*9];
    } else {
        const float* p=((w==4)?m1:m2)+(size_t)n*CH;
        v0=p[k0]; v1=p[k0+1]; v2=p[k0+8]; v3=p[k0+9];
    }
    size_t base=(size_t)(w*8+kc)*16384;
    uint32_t fo=((uint32_t)(ks*32+nt)*32+lane)*8;
    *(uint2*)(g_wb+base+fo)=make_uint2(packh2(v0,v1),packh2(v2,v3));
}

// ---------- GEMM: D[64][256] = A[64][256] x W^T, single-pass fp16 ----------
__device__ __forceinline__ void run_gemm(int w,uint32_t smb,int tid,
                                         int mq,int nh,int g,int q,float d[16][4]){
#pragma unroll
    for(int i=0;i<16;i++){d[i][0]=0.f;d[i][1]=0.f;d[i][2]=0.f;d[i][3]=0.f;}
    {   const unsigned char* src=g_wb+(size_t)(w*8)*16384;
        uint32_t dst=smb+OFF_B;
#pragma unroll
        for(int j=0;j<4;j++) cp16(dst+j*4096+tid*16, src+j*4096+tid*16);
        asm volatile("cp.async.commit_group;");
    }
    uint32_t aH=smb+OFF_A+(mq*16+g)*528;
#pragma unroll 1
    for(int kc=0;kc<8;kc++){
        if(kc<7){
            const unsigned char* src=g_wb+(size_t)(w*8+kc+1)*16384;
            uint32_t dst=smb+OFF_B+((kc+1)&1)*16384;
#pragma unroll
            for(int j=0;j<4;j++) cp16(dst+j*4096+tid*16, src+j*4096+tid*16);
            asm volatile("cp.async.commit_group;");
            asm volatile("cp.async.wait_group 1;");
        } else asm volatile("cp.async.wait_group 0;");
        __syncthreads();
        uint32_t bb=smb+OFF_B+(kc&1)*16384;
#pragma unroll
        for(int ks=0;ks<2;ks++){
            int koff=(kc*32+ks*16+q*2)*2;
            uint32_t ah[4];
            ah[0]=lds32(aH+koff);       ah[1]=lds32(aH+koff+8*528);
            ah[2]=lds32(aH+koff+16);    ah[3]=lds32(aH+koff+8*528+16);
            uint32_t fb=bb+((uint32_t)(ks*32+nh*16)*32+(tid&31))*8;
#pragma unroll
            for(int i=0;i<16;i++){
                uint32_t b0,b1;
                lds64(fb+i*256,b0,b1);
                mma16816(d[i],ah,b0,b1);
            }
        }
        __syncthreads();
    }
}

// ---------- fused main kernel ----------
__global__ __launch_bounds__(256,2) void main_kernel(
    const int* __restrict__ pts,
    const float* __restrict__ gn1w,const float* __restrict__ gn1b,
    const float* __restrict__ c1b,
    const float* __restrict__ gn2w,const float* __restrict__ gn2b,
    const float* __restrict__ c2b,
    const float* __restrict__ clsw,const float* __restrict__ clsb,
    const float* __restrict__ mb1,const float* __restrict__ mb2,
    const float* __restrict__ mw3,const float* __restrict__ mb3,
    float* __restrict__ out)
{
    extern __shared__ __align__(16) unsigned char smp[];
    uint32_t smb=s2u(smp);
    int tid=threadIdx.x, lane=tid&31, wid=tid>>5;
    int mq=wid&3, nh=wid>>2, g=lane>>2, q=lane&3;
    int row_base=blockIdx.x*MT;
    float* w3s=(float*)(smp+OFF_W3);
    float* cws=(float*)(smp+OFF_CW);
    float* red=(float*)(smp+OFF_RED);

    for(int i=tid;i<1024;i+=256) w3s[i]=mw3[i];
    for(int i=tid;i<512;i+=256)  cws[i]=clsw[i];
    if(tid<MT){
        int r=row_base+tid;
        int p0=pts[r*2], p1=pts[r*2+1];
        ((int*)(smp+OFF_LIN))[tid]=((r>>11)*HW+((p0>>3)*32+(p1>>3)))*CH;
    }
    __syncthreads();

    // gather -> X(fp16) ; GN1[0]+SiLU -> A(fp16)
    {
        int row=tid>>2, t4=tid&3;
        const float* src=g_t+((const int*)(smp+OFF_LIN))[row]+t4*64;
        float v[64];
#pragma unroll
        for(int i=0;i<16;i++) *(float4*)(v+i*4)=*(const float4*)(src+i*4);
        uint32_t xbb=smb+OFF_X+row*528+t4*128;
#pragma unroll
        for(int j2=0;j2<32;j2++) sts32(xbb+j2*4,packh2(v[2*j2],v[2*j2+1]));
#pragma unroll
        for(int gr=0;gr<8;gr++){
            float s=0.f,vv=0.f;
#pragma unroll
            for(int j=0;j<8;j++) s+=v[gr*8+j];
            float mean=s*0.125f;
#pragma unroll
            for(int j=0;j<8;j++){float e=v[gr*8+j]-mean; vv+=e*e;}
            float rs=rsqrtf(vv*0.125f+1e-5f);
#pragma unroll
            for(int j=0;j<8;j++){
                int n=t4*64+gr*8+j;
                v[gr*8+j]=silu((v[gr*8+j]-mean)*rs*gn1w[n]+gn1b[n]);
            }
        }
        uint32_t ahb=smb+OFF_A+row*528+t4*128;
#pragma unroll
        for(int j2=0;j2<32;j2++) sts32(ahb+j2*4,packh2(v[2*j2],v[2*j2+1]));
    }
    __syncthreads();

    float d[16][4];
    int mg=mq*16+g;
    uint32_t ah_w=smb+OFF_A+mg*528;
    uint32_t xs_w=smb+OFF_X+mg*528;

#pragma unroll 1
    for(int L=0;L<2;++L){
        run_gemm(L*2+0,smb,tid,mq,nh,g,q,d);               // conv1
        const float* b1=c1b+L*CH; const float* g2w=gn2w+L*CH; const float* g2b=gn2b+L*CH;
#pragma unroll
        for(int i=0;i<16;i++){
            int n0=(nh*16+i)*8+q*2;
            d[i][0]+=b1[n0]; d[i][1]+=b1[n0+1]; d[i][2]+=b1[n0]; d[i][3]+=b1[n0+1];
            GNPAIR(d[i][0],d[i][1],g2w,g2b,n0);
            GNPAIR(d[i][2],d[i][3],g2w,g2b,n0);
            sts32(ah_w+n0*2,packh2(d[i][0],d[i][1]));
            sts32(ah_w+8*528+n0*2,packh2(d[i][2],d[i][3]));
        }
        __syncthreads();

        run_gemm(L*2+1,smb,tid,mq,nh,g,q,d);               // conv2
        const float* b2=c2b+L*CH; const float* g1w=gn1w+CH; const float* g1b=gn1b+CH;
#pragma unroll
        for(int i=0;i<16;i++){
            int n0=(nh*16+i)*8+q*2;
            float2 xf=unph2(lds32(xs_w+n0*2));
            d[i][0]+=b2[n0]+xf.x; d[i][1]+=b2[n0+1]+xf.y;
            sts32(xs_w+n0*2,packh2(d[i][0],d[i][1]));
            xf=unph2(lds32(xs_w+8*528+n0*2));
            d[i][2]+=b2[n0]+xf.x; d[i][3]+=b2[n0+1]+xf.y;
            sts32(xs_w+8*528+n0*2,packh2(d[i][2],d[i][3]));
            if(L==0){ GNPAIR(d[i][0],d[i][1],g1w,g1b,n0); GNPAIR(d[i][2],d[i][3],g1w,g1b,n0); }
            sts32(ah_w+n0*2,packh2(d[i][0],d[i][1]));
            sts32(ah_w+8*528+n0*2,packh2(d[i][2],d[i][3]));
        }
        __syncthreads();
    }

    run_gemm(4,smb,tid,mq,nh,g,q,d);                       // mlp1
#pragma unroll
    for(int i=0;i<16;i++){
        int n0=(nh*16+i)*8+q*2;
        d[i][0]=fmaxf(d[i][0]+mb1[n0],0.f);   d[i][1]=fmaxf(d[i][1]+mb1[n0+1],0.f);
        d[i][2]=fmaxf(d[i][2]+mb1[n0],0.f);   d[i][3]=fmaxf(d[i][3]+mb1[n0+1],0.f);
        sts32(ah_w+n0*2,packh2(d[i][0],d[i][1]));
        sts32(ah_w+8*528+n0*2,packh2(d[i][2],d[i][3]));
    }
    __syncthreads();

    run_gemm(5,smb,tid,mq,nh,g,q,d);                       // mlp2
    {
        float bg[4]={0,0,0,0}, bh[4]={0,0,0,0};
#pragma unroll
        for(int i=0;i<16;i++){
            int n0=(nh*16+i)*8+q*2;
            float t0=fmaxf(d[i][0]+mb2[n0],0.f),  t1=fmaxf(d[i][1]+mb2[n0+1],0.f);
            float t2=fmaxf(d[i][2]+mb2[n0],0.f),  t3=fmaxf(d[i][3]+mb2[n0+1],0.f);
#pragma unroll
            for(int s=0;s<4;s++){
                float w0=w3s[s*256+n0], w1=w3s[s*256+n0+1];
                bg[s]+=t0*w0+t1*w1;
                bh[s]+=t2*w0+t3*w1;
            }
        }
#pragma unroll
        for(int s=0;s<4;s++){
            bg[s]+=__shfl_xor_sync(0xffffffffu,bg[s],1); bg[s]+=__shfl_xor_sync(0xffffffffu,bg[s],2);
            bh[s]+=__shfl_xor_sync(0xffffffffu,bh[s],1); bh[s]+=__shfl_xor_sync(0xffffffffu,bh[s],2);
        }
        if(q==0){
#pragma unroll
            for(int s=0;s<4;s++){
                red[mg*16+nh*8+s]=bg[s];
                red[(mg+8)*16+nh*8+s]=bh[s];
            }
        }
    }
    __syncthreads();

    // heads out
    if(tid<MT){
        size_t row=(size_t)row_base+tid;
#pragma unroll
        for(int s=0;s<4;s++){
            float a=red[tid*16+s]+red[tid*16+8+s]+mb3[s];
            out[131072+row*4+s]=1.f/(1.f+__expf(-a));
        }
    }
    {
        int row=tid>>2, t4=tid&3;
        uint32_t xbb=smb+OFF_X+row*528+t4*128;
        float c0=0.f,c1=0.f;
#pragma unroll 8
        for(int j=0;j<32;j++){
            float2 xf=unph2(lds32(xbb+j*4));
            int k=t4*64+j*2;
            c0+=xf.x*cws[k]+xf.y*cws[k+1];
            c1+=xf.x*cws[256+k]+xf.y*cws[256+k+1];
        }
        c0+=__shfl_xor_sync(0xffffffffu,c0,1); c0+=__shfl_xor_sync(0xffffffffu,c0,2);
        c1+=__shfl_xor_sync(0xffffffffu,c1,1); c1+=__shfl_xor_sync(0xffffffffu,c1,2);
        if(t4==0){
            size_t r=(size_t)row_base+row;
            out[r*2+0]=c0+clsb[0];
            out[r*2+1]=c1+clsb[1];
        }
    }
}

// ---------- launch ----------
extern "C" void kernel_launch(void* const* d_in, const int* in_sizes, int n_in,
                              void* d_out, int out_size){
    const float* gimage=(const float*)d_in[0];
    const int*   pts   =(const int*)  d_in[1];
    const float* gn1w=(const float*)d_in[2],  *gn1b=(const float*)d_in[3];
    const float* c1w =(const float*)d_in[4],  *c1b =(const float*)d_in[5];
    const float* gn2w=(const float*)d_in[6],  *gn2b=(const float*)d_in[7];
    const float* c2w =(const float*)d_in[8],  *c2b =(const float*)d_in[9];
    const float* clsw=(const float*)d_in[10], *clsb=(const float*)d_in[11];
    const float* mw1 =(const float*)d_in[12], *mb1 =(const float*)d_in[13];
    const float* mw2 =(const float*)d_in[14], *mb2 =(const float*)d_in[15];
    const float* mw3 =(const float*)d_in[16], *mb3 =(const float*)d_in[17];
    float* out=(float*)d_out;

    cudaFuncSetAttribute(main_kernel, cudaFuncAttributeMaxDynamicSharedMemorySize, SMEM_TOTAL);

    dim3 tgrid(HW/32, CH/32, BS), tblk(32,8);
    transpose_kernel<<<tgrid,tblk>>>(gimage);
    prep_kernel<<<384,256>>>(c1w,c2w,mw1,mw2);
    main_kernel<<<NBLK,256,SMEM_TOTAL>>>(pts,gn1w,gn1b,c1b,gn2w,gn2b,c2b,
                                         clsw,clsb,mb1,mb2,mw3,mb3,out);
}

// round 11
// speedup vs baseline: 4.5308x; 1.2544x over previous
#include <cuda_runtime.h>
#include <cuda_fp16.h>
#include <stdint.h>

#define HW 1024
#define CH 256
#define BS 32
#define NROWS 65536
#define MT 64
#define NBLK (NROWS/MT)

#define OFF_X   0                 // fp16 [64][264]
#define OFF_A   33792             // fp16 [64][264]
#define OFF_RED 67584             // 64*32 f32
#define OFF_W3  75776             // 1024 f32
#define OFF_CW  79872             // 512 f32
#define OFF_LIN 81920             // 64 ints
#define SMEM_TOTAL 82176

__device__ float g_t[(size_t)BS*HW*CH];                       // [b][p][c]
__device__ __align__(16) unsigned char g_wb[(size_t)6*8*16384]; // frag-packed fp16 weights

// ---------- helpers ----------
__device__ __forceinline__ uint32_t s2u(const void* p){
    uint32_t a; asm("{ .reg .u64 t; cvta.to.shared.u64 t, %1; cvt.u32.u64 %0, t; }":"=r"(a):"l"(p)); return a;
}
__device__ __forceinline__ uint32_t lds32(uint32_t a){
    uint32_t v; asm volatile("ld.shared.b32 %0,[%1];":"=r"(v):"r"(a)); return v;
}
__device__ __forceinline__ void sts32(uint32_t a,uint32_t v){
    asm volatile("st.shared.b32 [%0],%1;"::"r"(a),"r"(v));
}
__device__ __forceinline__ float silu(float x){ return x/(1.f+__expf(-x)); }
__device__ __forceinline__ uint32_t packh2(float f0,float f1){
    __half2 h=__floats2half2_rn(f0,f1); return *(uint32_t*)&h;
}
__device__ __forceinline__ float2 unph2(uint32_t u){
    return __half22float2(*(__half2*)&u);
}
__device__ __forceinline__ void mma16816(float* d,const uint32_t* a,uint32_t b0,uint32_t b1){
    asm volatile("mma.sync.aligned.m16n8k16.row.col.f32.f16.f16.f32 "
        "{%0,%1,%2,%3}, {%4,%5,%6,%7}, {%8,%9}, {%0,%1,%2,%3};"
        : "+f"(d[0]),"+f"(d[1]),"+f"(d[2]),"+f"(d[3])
        : "r"(a[0]),"r"(a[1]),"r"(a[2]),"r"(a[3]),"r"(b0),"r"(b1));
}
// GN over 8 channels spread across the 4 quad lanes (2 per lane)
#define GNPAIR(D0,D1,GW,GB,N0) { \
    float s_=(D0)+(D1); s_+=__shfl_xor_sync(0xffffffffu,s_,1); s_+=__shfl_xor_sync(0xffffffffu,s_,2); \
    float mn_=s_*0.125f, e0_=(D0)-mn_, e1_=(D1)-mn_; \
    float vv_=e0_*e0_+e1_*e1_; vv_+=__shfl_xor_sync(0xffffffffu,vv_,1); vv_+=__shfl_xor_sync(0xffffffffu,vv_,2); \
    float rs_=rsqrtf(vv_*0.125f+1e-5f); \
    (D0)=silu(e0_*rs_*(GW)[N0]+(GB)[N0]); (D1)=silu(e1_*rs_*(GW)[(N0)+1]+(GB)[(N0)+1]); }

// ---------- kernel 1: transpose [b][c][p] -> [b][p][c] ----------
__global__ void transpose_kernel(const float* __restrict__ g){
    __shared__ float tile[32][33];
    int b=blockIdx.z, p0=blockIdx.x*32, c0=blockIdx.y*32;
    int tx=threadIdx.x, ty=threadIdx.y;
    const float* src=g+(size_t)b*CH*HW;
    float* dst=g_t+(size_t)b*HW*CH;
#pragma unroll
    for(int i=0;i<4;i++) tile[ty+i*8][tx]=src[(size_t)(c0+ty+i*8)*HW+p0+tx];
    __syncthreads();
#pragma unroll
    for(int i=0;i<4;i++) dst[(size_t)(p0+ty+i*8)*CH+c0+tx]=tile[tx][ty+i*8];
}

// ---------- kernel 2: weights -> fp16 fragment-packed 16KB chunks ----------
__global__ void prep_kernel(const float* __restrict__ c1,const float* __restrict__ c2,
                            const float* __restrict__ m1,const float* __restrict__ m2){
    int gid=blockIdx.x*256+threadIdx.x;          // 98304 total
    int lane=gid&31, nt=(gid>>5)&31, ks=(gid>>10)&1, kc=(gid>>11)&7, w=gid>>14;
    int q=lane&3, g=lane>>2;
    int n=nt*8+g;
    int k0=kc*32+ks*16+q*2;
    float v0,v1,v2,v3;
    if(w<4){
        const float* s=(w&1)?c2:c1; int L=w>>1;
        const float* p=s+((size_t)(L*CH+n)*CH)*9+4;
        v0=p[(size_t)k0*9]; v1=p[(size_t)(k0+1)*9];
        v2=p[(size_t)(k0+8)*9]; v3=p[(size_t)(k0+9)*9];
    } else {
        const float* p=((w==4)?m1:m2)+(size_t)n*CH;
        v0=p[k0]; v1=p[k0+1]; v2=p[k0+8]; v3=p[k0+9];
    }
    size_t base=(size_t)(w*8+kc)*16384;
    uint32_t fo=((uint32_t)(ks*32+nt)*32+lane)*8;
    *(uint2*)(g_wb+base+fo)=make_uint2(packh2(v0,v1),packh2(v2,v3));
}

// ---------- GEMM: D[64][256] = A[64][256] x W^T; B via LDG->reg ----------
// warp nh owns all 4 m-frags x 4 n-tiles (cols nh*32..nh*32+31).
__device__ __forceinline__ void run_gemm(int w,uint32_t smb,int nh,int g,int q,int lane,
                                         float d[16][4]){
#pragma unroll
    for(int i=0;i<16;i++){d[i][0]=0.f;d[i][1]=0.f;d[i][2]=0.f;d[i][3]=0.f;}
    const unsigned char* wb=g_wb+(size_t)w*131072;
    uint32_t lo=((uint32_t)nh<<10)+((uint32_t)lane<<3);   // nh*4*256 + lane*8
    uint2 bp[2][4];
#pragma unroll
    for(int lt=0;lt<4;lt++){
        bp[0][lt]=__ldg((const uint2*)(wb + lo + lt*256));
        bp[1][lt]=__ldg((const uint2*)(wb + 8192 + lo + lt*256));
    }
#pragma unroll
    for(int kst=0;kst<16;kst++){
        uint32_t ak=smb+OFF_A+(uint32_t)(kst*16+q*2)*2;
        uint32_t ah[4][4];
#pragma unroll
        for(int mf=0;mf<4;mf++){
            uint32_t ab=ak+(uint32_t)(mf*16+g)*528;
            ah[mf][0]=lds32(ab);     ah[mf][1]=lds32(ab+8*528);
            ah[mf][2]=lds32(ab+16);  ah[mf][3]=lds32(ab+8*528+16);
        }
#pragma unroll
        for(int lt=0;lt<4;lt++){
            uint2 bf=bp[kst&1][lt];
#pragma unroll
            for(int mf=0;mf<4;mf++) mma16816(d[mf*4+lt],ah[mf],bf.x,bf.y);
        }
        if(kst<14){
            int kn=kst+2;
            const unsigned char* src=wb+(kn>>1)*16384+(kn&1)*8192+lo;
#pragma unroll
            for(int lt=0;lt<4;lt++) bp[kst&1][lt]=__ldg((const uint2*)(src+lt*256));
        }
    }
}

// ---------- fused main kernel ----------
__global__ __launch_bounds__(256,2) void main_kernel(
    const int* __restrict__ pts,
    const float* __restrict__ gn1w,const float* __restrict__ gn1b,
    const float* __restrict__ c1b,
    const float* __restrict__ gn2w,const float* __restrict__ gn2b,
    const float* __restrict__ c2b,
    const float* __restrict__ clsw,const float* __restrict__ clsb,
    const float* __restrict__ mb1,const float* __restrict__ mb2,
    const float* __restrict__ mw3,const float* __restrict__ mb3,
    float* __restrict__ out)
{
    extern __shared__ __align__(16) unsigned char smp[];
    uint32_t smb=s2u(smp);
    int tid=threadIdx.x, lane=tid&31, nh=tid>>5;
    int g=lane>>2, q=lane&3;
    int row_base=blockIdx.x*MT;
    float* w3s=(float*)(smp+OFF_W3);
    float* cws=(float*)(smp+OFF_CW);
    float* red=(float*)(smp+OFF_RED);

    for(int i=tid;i<1024;i+=256) w3s[i]=mw3[i];
    for(int i=tid;i<512;i+=256)  cws[i]=clsw[i];
    if(tid<MT){
        int r=row_base+tid;
        int p0=pts[r*2], p1=pts[r*2+1];
        ((int*)(smp+OFF_LIN))[tid]=((r>>11)*HW+((p0>>3)*32+(p1>>3)))*CH;
    }
    __syncthreads();

    // gather -> X(fp16) ; GN1[0]+SiLU -> A(fp16)
    {
        int row=tid>>2, t4=tid&3;
        const float* src=g_t+((const int*)(smp+OFF_LIN))[row]+t4*64;
        float v[64];
#pragma unroll
        for(int i=0;i<16;i++) *(float4*)(v+i*4)=*(const float4*)(src+i*4);
        uint32_t xbb=smb+OFF_X+row*528+t4*128;
#pragma unroll
        for(int j2=0;j2<32;j2++) sts32(xbb+j2*4,packh2(v[2*j2],v[2*j2+1]));
#pragma unroll
        for(int gr=0;gr<8;gr++){
            float s=0.f,vv=0.f;
#pragma unroll
            for(int j=0;j<8;j++) s+=v[gr*8+j];
            float mean=s*0.125f;
#pragma unroll
            for(int j=0;j<8;j++){float e=v[gr*8+j]-mean; vv+=e*e;}
            float rs=rsqrtf(vv*0.125f+1e-5f);
#pragma unroll
            for(int j=0;j<8;j++){
                int n=t4*64+gr*8+j;
                v[gr*8+j]=silu((v[gr*8+j]-mean)*rs*gn1w[n]+gn1b[n]);
            }
        }
        uint32_t ahb=smb+OFF_A+row*528+t4*128;
#pragma unroll
        for(int j2=0;j2<32;j2++) sts32(ahb+j2*4,packh2(v[2*j2],v[2*j2+1]));
    }
    __syncthreads();

    float d[16][4];

#pragma unroll 1
    for(int L=0;L<2;++L){
        run_gemm(L*2+0,smb,nh,g,q,lane,d);                 // conv1
        __syncthreads();
        const float* b1=c1b+L*CH; const float* g2w=gn2w+L*CH; const float* g2b=gn2b+L*CH;
#pragma unroll
        for(int e=0;e<16;e++){
            int mf=e>>2, lt=e&3;
            int n0=nh*32+lt*8+q*2;
            uint32_t ro=(uint32_t)(mf*16+g)*528+(uint32_t)n0*2;
            d[e][0]+=b1[n0]; d[e][1]+=b1[n0+1]; d[e][2]+=b1[n0]; d[e][3]+=b1[n0+1];
            GNPAIR(d[e][0],d[e][1],g2w,g2b,n0);
            GNPAIR(d[e][2],d[e][3],g2w,g2b,n0);
            sts32(smb+OFF_A+ro,packh2(d[e][0],d[e][1]));
            sts32(smb+OFF_A+ro+8*528,packh2(d[e][2],d[e][3]));
        }
        __syncthreads();

        run_gemm(L*2+1,smb,nh,g,q,lane,d);                 // conv2
        __syncthreads();
        const float* b2=c2b+L*CH; const float* g1w=gn1w+CH; const float* g1b=gn1b+CH;
#pragma unroll
        for(int e=0;e<16;e++){
            int mf=e>>2, lt=e&3;
            int n0=nh*32+lt*8+q*2;
            uint32_t ro=(uint32_t)(mf*16+g)*528+(uint32_t)n0*2;
            float2 xf=unph2(lds32(smb+OFF_X+ro));
            d[e][0]+=b2[n0]+xf.x; d[e][1]+=b2[n0+1]+xf.y;
            sts32(smb+OFF_X+ro,packh2(d[e][0],d[e][1]));
            xf=unph2(lds32(smb+OFF_X+ro+8*528));
            d[e][2]+=b2[n0]+xf.x; d[e][3]+=b2[n0+1]+xf.y;
            sts32(smb+OFF_X+ro+8*528,packh2(d[e][2],d[e][3]));
            if(L==0){ GNPAIR(d[e][0],d[e][1],g1w,g1b,n0); GNPAIR(d[e][2],d[e][3],g1w,g1b,n0); }
            sts32(smb+OFF_A+ro,packh2(d[e][0],d[e][1]));
            sts32(smb+OFF_A+ro+8*528,packh2(d[e][2],d[e][3]));
        }
        __syncthreads();
    }

    run_gemm(4,smb,nh,g,q,lane,d);                         // mlp1
    __syncthreads();
#pragma unroll
    for(int e=0;e<16;e++){
        int mf=e>>2, lt=e&3;
        int n0=nh*32+lt*8+q*2;
        uint32_t ro=(uint32_t)(mf*16+g)*528+(uint32_t)n0*2;
        d[e][0]=fmaxf(d[e][0]+mb1[n0],0.f);   d[e][1]=fmaxf(d[e][1]+mb1[n0+1],0.f);
        d[e][2]=fmaxf(d[e][2]+mb1[n0],0.f);   d[e][3]=fmaxf(d[e][3]+mb1[n0+1],0.f);
        sts32(smb+OFF_A+ro,packh2(d[e][0],d[e][1]));
        sts32(smb+OFF_A+ro+8*528,packh2(d[e][2],d[e][3]));
    }
    __syncthreads();

    run_gemm(5,smb,nh,g,q,lane,d);                         // mlp2
    {
        float bxa[4][4], bxb[4][4];
#pragma unroll
        for(int mf=0;mf<4;mf++)
#pragma unroll
            for(int s=0;s<4;s++){ bxa[mf][s]=0.f; bxb[mf][s]=0.f; }
#pragma unroll
        for(int e=0;e<16;e++){
            int mf=e>>2, lt=e&3;
            int n0=nh*32+lt*8+q*2;
            float t0=fmaxf(d[e][0]+mb2[n0],0.f),  t1=fmaxf(d[e][1]+mb2[n0+1],0.f);
            float t2=fmaxf(d[e][2]+mb2[n0],0.f),  t3=fmaxf(d[e][3]+mb2[n0+1],0.f);
#pragma unroll
            for(int s=0;s<4;s++){
                float w0=w3s[s*256+n0], w1=w3s[s*256+n0+1];
                bxa[mf][s]+=t0*w0+t1*w1;
                bxb[mf][s]+=t2*w0+t3*w1;
            }
        }
#pragma unroll
        for(int mf=0;mf<4;mf++)
#pragma unroll
            for(int s=0;s<4;s++){
                bxa[mf][s]+=__shfl_xor_sync(0xffffffffu,bxa[mf][s],1);
                bxa[mf][s]+=__shfl_xor_sync(0xffffffffu,bxa[mf][s],2);
                bxb[mf][s]+=__shfl_xor_sync(0xffffffffu,bxb[mf][s],1);
                bxb[mf][s]+=__shfl_xor_sync(0xffffffffu,bxb[mf][s],2);
            }
        if(q==0){
#pragma unroll
            for(int mf=0;mf<4;mf++)
#pragma unroll
                for(int s=0;s<4;s++){
                    red[(mf*16+g)*32+nh*4+s]=bxa[mf][s];
                    red[(mf*16+g+8)*32+nh*4+s]=bxb[mf][s];
                }
        }
    }
    __syncthreads();

    // heads out
    if(tid<MT){
        size_t row=(size_t)row_base+tid;
#pragma unroll
        for(int s=0;s<4;s++){
            float a=mb3[s];
#pragma unroll
            for(int h=0;h<8;h++) a+=red[tid*32+h*4+s];
            out[131072+row*4+s]=1.f/(1.f+__expf(-a));
        }
    }
    {
        int row=tid>>2, t4=tid&3;
        uint32_t xbb=smb+OFF_X+row*528+t4*128;
        float c0=0.f,c1=0.f;
#pragma unroll 8
        for(int j=0;j<32;j++){
            float2 xf=unph2(lds32(xbb+j*4));
            int k=t4*64+j*2;
            c0+=xf.x*cws[k]+xf.y*cws[k+1];
            c1+=xf.x*cws[256+k]+xf.y*cws[256+k+1];
        }
        c0+=__shfl_xor_sync(0xffffffffu,c0,1); c0+=__shfl_xor_sync(0xffffffffu,c0,2);
        c1+=__shfl_xor_sync(0xffffffffu,c1,1); c1+=__shfl_xor_sync(0xffffffffu,c1,2);
        if(t4==0){
            size_t r=(size_t)row_base+row;
            out[r*2+0]=c0+clsb[0];
            out[r*2+1]=c1+clsb[1];
        }
    }
}

// ---------- launch ----------
extern "C" void kernel_launch(void* const* d_in, const int* in_sizes, int n_in,
                              void* d_out, int out_size){
    const float* gimage=(const float*)d_in[0];
    const int*   pts   =(const int*)  d_in[1];
    const float* gn1w=(const float*)d_in[2],  *gn1b=(const float*)d_in[3];
    const float* c1w =(const float*)d_in[4],  *c1b =(const float*)d_in[5];
    const float* gn2w=(const float*)d_in[6],  *gn2b=(const float*)d_in[7];
    const float* c2w =(const float*)d_in[8],  *c2b =(const float*)d_in[9];
    const float* clsw=(const float*)d_in[10], *clsb=(const float*)d_in[11];
    const float* mw1 =(const float*)d_in[12], *mb1 =(const float*)d_in[13];
    const float* mw2 =(const float*)d_in[14], *mb2 =(const float*)d_in[15];
    const float* mw3 =(const float*)d_in[16], *mb3 =(const float*)d_in[17];
    float* out=(float*)d_out;

    cudaFuncSetAttribute(main_kernel, cudaFuncAttributeMaxDynamicSharedMemorySize, SMEM_TOTAL);

    dim3 tgrid(HW/32, CH/32, BS), tblk(32,8);
    transpose_kernel<<<tgrid,tblk>>>(gimage);
    prep_kernel<<<384,256>>>(c1w,c2w,mw1,mw2);
    main_kernel<<<NBLK,256,SMEM_TOTAL>>>(pts,gn1w,gn1b,c1b,gn2w,gn2b,c2b,
                                         clsw,clsb,mb1,mb2,mw3,mb3,out);
}

// round 12
// speedup vs baseline: 4.6152x; 1.0186x over previous
#include <cuda_runtime.h>
#include <cuda_fp16.h>
#include <stdint.h>

#define HW 1024
#define CH 256
#define BS 32
#define NROWS 65536
#define MT 64
#define NBLK (NROWS/MT)

#define OFF_X   0                 // fp16 [64][264]
#define OFF_A   33792             // fp16 [64][264]
#define OFF_RED 67584             // 64*32 f32
#define OFF_W3  75776             // 1024 f32
#define OFF_CW  79872             // 512 f32
#define OFF_LIN 81920             // 64 ints
#define SMEM_TOTAL 82176

__device__ float g_t[(size_t)BS*HW*CH];                       // [b][p][c]
__device__ __align__(16) unsigned char g_wb[(size_t)6*8*16384]; // frag-packed fp16 weights

// ---------- helpers ----------
__device__ __forceinline__ uint32_t s2u(const void* p){
    uint32_t a; asm("{ .reg .u64 t; cvta.to.shared.u64 t, %1; cvt.u32.u64 %0, t; }":"=r"(a):"l"(p)); return a;
}
__device__ __forceinline__ uint32_t lds32(uint32_t a){
    uint32_t v; asm volatile("ld.shared.b32 %0,[%1];":"=r"(v):"r"(a)); return v;
}
__device__ __forceinline__ void sts32(uint32_t a,uint32_t v){
    asm volatile("st.shared.b32 [%0],%1;"::"r"(a),"r"(v));
}
__device__ __forceinline__ void ldsm4(uint32_t addr,uint32_t* r){
    asm volatile("ldmatrix.sync.aligned.m8n8.x4.shared.b16 {%0,%1,%2,%3}, [%4];"
        : "=r"(r[0]),"=r"(r[1]),"=r"(r[2]),"=r"(r[3]) : "r"(addr));
}
__device__ __forceinline__ float silu(float x){ return x/(1.f+__expf(-x)); }
__device__ __forceinline__ uint32_t packh2(float f0,float f1){
    __half2 h=__floats2half2_rn(f0,f1); return *(uint32_t*)&h;
}
__device__ __forceinline__ float2 unph2(uint32_t u){
    return __half22float2(*(__half2*)&u);
}
__device__ __forceinline__ void mma16816(float* d,const uint32_t* a,uint32_t b0,uint32_t b1){
    asm volatile("mma.sync.aligned.m16n8k16.row.col.f32.f16.f16.f32 "
        "{%0,%1,%2,%3}, {%4,%5,%6,%7}, {%8,%9}, {%0,%1,%2,%3};"
        : "+f"(d[0]),"+f"(d[1]),"+f"(d[2]),"+f"(d[3])
        : "r"(a[0]),"r"(a[1]),"r"(a[2]),"r"(a[3]),"r"(b0),"r"(b1));
}
// GN over 8 channels spread across the 4 quad lanes (2 per lane)
#define GNPAIR(D0,D1,GW,GB,N0) { \
    float s_=(D0)+(D1); s_+=__shfl_xor_sync(0xffffffffu,s_,1); s_+=__shfl_xor_sync(0xffffffffu,s_,2); \
    float mn_=s_*0.125f, e0_=(D0)-mn_, e1_=(D1)-mn_; \
    float vv_=e0_*e0_+e1_*e1_; vv_+=__shfl_xor_sync(0xffffffffu,vv_,1); vv_+=__shfl_xor_sync(0xffffffffu,vv_,2); \
    float rs_=rsqrtf(vv_*0.125f+1e-5f); \
    (D0)=silu(e0_*rs_*(GW)[N0]+(GB)[N0]); (D1)=silu(e1_*rs_*(GW)[(N0)+1]+(GB)[(N0)+1]); }

// ---------- kernel 1: transpose [b][c][p] -> [b][p][c] ----------
__global__ void transpose_kernel(const float* __restrict__ g){
    __shared__ float tile[32][33];
    int b=blockIdx.z, p0=blockIdx.x*32, c0=blockIdx.y*32;
    int tx=threadIdx.x, ty=threadIdx.y;
    const float* src=g+(size_t)b*CH*HW;
    float* dst=g_t+(size_t)b*HW*CH;
#pragma unroll
    for(int i=0;i<4;i++) tile[ty+i*8][tx]=src[(size_t)(c0+ty+i*8)*HW+p0+tx];
    __syncthreads();
#pragma unroll
    for(int i=0;i<4;i++) dst[(size_t)(p0+ty+i*8)*CH+c0+tx]=tile[tx][ty+i*8];
}

// ---------- kernel 2: weights -> fp16 fragment-packed 16KB chunks ----------
__global__ void prep_kernel(const float* __restrict__ c1,const float* __restrict__ c2,
                            const float* __restrict__ m1,const float* __restrict__ m2){
    int gid=blockIdx.x*256+threadIdx.x;          // 98304 total
    int lane=gid&31, nt=(gid>>5)&31, ks=(gid>>10)&1, kc=(gid>>11)&7, w=gid>>14;
    int q=lane&3, g=lane>>2;
    int n=nt*8+g;
    int k0=kc*32+ks*16+q*2;
    float v0,v1,v2,v3;
    if(w<4){
        const float* s=(w&1)?c2:c1; int L=w>>1;
        const float* p=s+((size_t)(L*CH+n)*CH)*9+4;
        v0=p[(size_t)k0*9]; v1=p[(size_t)(k0+1)*9];
        v2=p[(size_t)(k0+8)*9]; v3=p[(size_t)(k0+9)*9];
    } else {
        const float* p=((w==4)?m1:m2)+(size_t)n*CH;
        v0=p[k0]; v1=p[k0+1]; v2=p[k0+8]; v3=p[k0+9];
    }
    size_t base=(size_t)(w*8+kc)*16384;
    uint32_t fo=((uint32_t)(ks*32+nt)*32+lane)*8;
    *(uint2*)(g_wb+base+fo)=make_uint2(packh2(v0,v1),packh2(v2,v3));
}

// ---------- GEMM: D[64][256] = A[64][256] x W^T; B LDG->reg, A ldmatrix -----
// warp nh owns all 4 m-frags x 4 n-tiles (cols nh*32..nh*32+31).
__device__ __forceinline__ void run_gemm(int w,uint32_t smb,int nh,int lane,
                                         float d[16][4]){
#pragma unroll
    for(int i=0;i<16;i++){d[i][0]=0.f;d[i][1]=0.f;d[i][2]=0.f;d[i][3]=0.f;}
    const unsigned char* wb=g_wb+(size_t)w*131072;
    uint32_t lo=((uint32_t)nh<<10)+((uint32_t)lane<<3);   // nh*4*256 + lane*8
    // ldmatrix lane base: row = lane&15 (stride 528), +16B for lanes>=16
    uint32_t abase=smb+OFF_A+(uint32_t)(lane&15)*528+((lane&16)?16u:0u);
    uint2 bp[2][4];
#pragma unroll
    for(int lt=0;lt<4;lt++){
        bp[0][lt]=__ldg((const uint2*)(wb + lo + lt*256));
        bp[1][lt]=__ldg((const uint2*)(wb + 8192 + lo + lt*256));
    }
#pragma unroll
    for(int kst=0;kst<16;kst++){
        uint32_t ak=abase+(uint32_t)kst*32;
        uint32_t ah[4][4];
#pragma unroll
        for(int mf=0;mf<4;mf++) ldsm4(ak+(uint32_t)mf*(16*528),ah[mf]);
#pragma unroll
        for(int lt=0;lt<4;lt++){
            uint2 bf=bp[kst&1][lt];
#pragma unroll
            for(int mf=0;mf<4;mf++) mma16816(d[mf*4+lt],ah[mf],bf.x,bf.y);
        }
        if(kst<14){
            int kn=kst+2;
            const unsigned char* src=wb+(kn>>1)*16384+(kn&1)*8192+lo;
#pragma unroll
            for(int lt=0;lt<4;lt++) bp[kst&1][lt]=__ldg((const uint2*)(src+lt*256));
        }
    }
}

// ---------- fused main kernel ----------
__global__ __launch_bounds__(256,2) void main_kernel(
    const int* __restrict__ pts,
    const float* __restrict__ gn1w,const float* __restrict__ gn1b,
    const float* __restrict__ c1b,
    const float* __restrict__ gn2w,const float* __restrict__ gn2b,
    const float* __restrict__ c2b,
    const float* __restrict__ clsw,const float* __restrict__ clsb,
    const float* __restrict__ mb1,const float* __restrict__ mb2,
    const float* __restrict__ mw3,const float* __restrict__ mb3,
    float* __restrict__ out)
{
    extern __shared__ __align__(16) unsigned char smp[];
    uint32_t smb=s2u(smp);
    int tid=threadIdx.x, lane=tid&31, nh=tid>>5;
    int g=lane>>2, q=lane&3;
    int row_base=blockIdx.x*MT;
    float* w3s=(float*)(smp+OFF_W3);
    float* cws=(float*)(smp+OFF_CW);
    float* red=(float*)(smp+OFF_RED);

    for(int i=tid;i<1024;i+=256) w3s[i]=mw3[i];
    for(int i=tid;i<512;i+=256)  cws[i]=clsw[i];
    if(tid<MT){
        int r=row_base+tid;
        int p0=pts[r*2], p1=pts[r*2+1];
        ((int*)(smp+OFF_LIN))[tid]=((r>>11)*HW+((p0>>3)*32+(p1>>3)))*CH;
    }
    __syncthreads();

    // gather -> X(fp16) ; GN1[0]+SiLU -> A(fp16)
    {
        int row=tid>>2, t4=tid&3;
        const float* src=g_t+((const int*)(smp+OFF_LIN))[row]+t4*64;
        float v[64];
#pragma unroll
        for(int i=0;i<16;i++) *(float4*)(v+i*4)=*(const float4*)(src+i*4);
        uint32_t xbb=smb+OFF_X+row*528+t4*128;
#pragma unroll
        for(int j2=0;j2<32;j2++) sts32(xbb+j2*4,packh2(v[2*j2],v[2*j2+1]));
#pragma unroll
        for(int gr=0;gr<8;gr++){
            float s=0.f,vv=0.f;
#pragma unroll
            for(int j=0;j<8;j++) s+=v[gr*8+j];
            float mean=s*0.125f;
#pragma unroll
            for(int j=0;j<8;j++){float e=v[gr*8+j]-mean; vv+=e*e;}
            float rs=rsqrtf(vv*0.125f+1e-5f);
#pragma unroll
            for(int j=0;j<8;j++){
                int n=t4*64+gr*8+j;
                v[gr*8+j]=silu((v[gr*8+j]-mean)*rs*gn1w[n]+gn1b[n]);
            }
        }
        uint32_t ahb=smb+OFF_A+row*528+t4*128;
#pragma unroll
        for(int j2=0;j2<32;j2++) sts32(ahb+j2*4,packh2(v[2*j2],v[2*j2+1]));
    }
    __syncthreads();

    float d[16][4];

#pragma unroll 1
    for(int L=0;L<2;++L){
        run_gemm(L*2+0,smb,nh,lane,d);                     // conv1
        __syncthreads();
        const float* b1=c1b+L*CH; const float* g2w=gn2w+L*CH; const float* g2b=gn2b+L*CH;
#pragma unroll
        for(int e=0;e<16;e++){
            int mf=e>>2, lt=e&3;
            int n0=nh*32+lt*8+q*2;
            uint32_t ro=(uint32_t)(mf*16+g)*528+(uint32_t)n0*2;
            d[e][0]+=b1[n0]; d[e][1]+=b1[n0+1]; d[e][2]+=b1[n0]; d[e][3]+=b1[n0+1];
            GNPAIR(d[e][0],d[e][1],g2w,g2b,n0);
            GNPAIR(d[e][2],d[e][3],g2w,g2b,n0);
            sts32(smb+OFF_A+ro,packh2(d[e][0],d[e][1]));
            sts32(smb+OFF_A+ro+8*528,packh2(d[e][2],d[e][3]));
        }
        __syncthreads();

        run_gemm(L*2+1,smb,nh,lane,d);                     // conv2
        __syncthreads();
        const float* b2=c2b+L*CH; const float* g1w=gn1w+CH; const float* g1b=gn1b+CH;
#pragma unroll
        for(int e=0;e<16;e++){
            int mf=e>>2, lt=e&3;
            int n0=nh*32+lt*8+q*2;
            uint32_t ro=(uint32_t)(mf*16+g)*528+(uint32_t)n0*2;
            float2 xf=unph2(lds32(smb+OFF_X+ro));
            d[e][0]+=b2[n0]+xf.x; d[e][1]+=b2[n0+1]+xf.y;
            sts32(smb+OFF_X+ro,packh2(d[e][0],d[e][1]));
            xf=unph2(lds32(smb+OFF_X+ro+8*528));
            d[e][2]+=b2[n0]+xf.x; d[e][3]+=b2[n0+1]+xf.y;
            sts32(smb+OFF_X+ro+8*528,packh2(d[e][2],d[e][3]));
            if(L==0){ GNPAIR(d[e][0],d[e][1],g1w,g1b,n0); GNPAIR(d[e][2],d[e][3],g1w,g1b,n0); }
            sts32(smb+OFF_A+ro,packh2(d[e][0],d[e][1]));
            sts32(smb+OFF_A+ro+8*528,packh2(d[e][2],d[e][3]));
        }
        __syncthreads();
    }

    run_gemm(4,smb,nh,lane,d);                             // mlp1
    __syncthreads();
#pragma unroll
    for(int e=0;e<16;e++){
        int mf=e>>2, lt=e&3;
        int n0=nh*32+lt*8+q*2;
        uint32_t ro=(uint32_t)(mf*16+g)*528+(uint32_t)n0*2;
        d[e][0]=fmaxf(d[e][0]+mb1[n0],0.f);   d[e][1]=fmaxf(d[e][1]+mb1[n0+1],0.f);
        d[e][2]=fmaxf(d[e][2]+mb1[n0],0.f);   d[e][3]=fmaxf(d[e][3]+mb1[n0+1],0.f);
        sts32(smb+OFF_A+ro,packh2(d[e][0],d[e][1]));
        sts32(smb+OFF_A+ro+8*528,packh2(d[e][2],d[e][3]));
    }
    __syncthreads();

    run_gemm(5,smb,nh,lane,d);                             // mlp2
    {
        float bxa[4][4], bxb[4][4];
#pragma unroll
        for(int mf=0;mf<4;mf++)
#pragma unroll
            for(int s=0;s<4;s++){ bxa[mf][s]=0.f; bxb[mf][s]=0.f; }
#pragma unroll
        for(int e=0;e<16;e++){
            int mf=e>>2, lt=e&3;
            int n0=nh*32+lt*8+q*2;
            float t0=fmaxf(d[e][0]+mb2[n0],0.f),  t1=fmaxf(d[e][1]+mb2[n0+1],0.f);
            float t2=fmaxf(d[e][2]+mb2[n0],0.f),  t3=fmaxf(d[e][3]+mb2[n0+1],0.f);
#pragma unroll
            for(int s=0;s<4;s++){
                float w0=w3s[s*256+n0], w1=w3s[s*256+n0+1];
                bxa[mf][s]+=t0*w0+t1*w1;
                bxb[mf][s]+=t2*w0+t3*w1;
            }
        }
#pragma unroll
        for(int mf=0;mf<4;mf++)
#pragma unroll
            for(int s=0;s<4;s++){
                bxa[mf][s]+=__shfl_xor_sync(0xffffffffu,bxa[mf][s],1);
                bxa[mf][s]+=__shfl_xor_sync(0xffffffffu,bxa[mf][s],2);
                bxb[mf][s]+=__shfl_xor_sync(0xffffffffu,bxb[mf][s],1);
                bxb[mf][s]+=__shfl_xor_sync(0xffffffffu,bxb[mf][s],2);
            }
        if(q==0){
#pragma unroll
            for(int mf=0;mf<4;mf++)
#pragma unroll
                for(int s=0;s<4;s++){
                    red[(mf*16+g)*32+nh*4+s]=bxa[mf][s];
                    red[(mf*16+g+8)*32+nh*4+s]=bxb[mf][s];
                }
        }
    }
    __syncthreads();

    // heads out
    if(tid<MT){
        size_t row=(size_t)row_base+tid;
#pragma unroll
        for(int s=0;s<4;s++){
            float a=mb3[s];
#pragma unroll
            for(int h=0;h<8;h++) a+=red[tid*32+h*4+s];
            out[131072+row*4+s]=1.f/(1.f+__expf(-a));
        }
    }
    {
        int row=tid>>2, t4=tid&3;
        uint32_t xbb=smb+OFF_X+row*528+t4*128;
        float c0=0.f,c1=0.f;
#pragma unroll 8
        for(int j=0;j<32;j++){
            float2 xf=unph2(lds32(xbb+j*4));
            int k=t4*64+j*2;
            c0+=xf.x*cws[k]+xf.y*cws[k+1];
            c1+=xf.x*cws[256+k]+xf.y*cws[256+k+1];
        }
        c0+=__shfl_xor_sync(0xffffffffu,c0,1); c0+=__shfl_xor_sync(0xffffffffu,c0,2);
        c1+=__shfl_xor_sync(0xffffffffu,c1,1); c1+=__shfl_xor_sync(0xffffffffu,c1,2);
        if(t4==0){
            size_t r=(size_t)row_base+row;
            out[r*2+0]=c0+clsb[0];
            out[r*2+1]=c1+clsb[1];
        }
    }
}

// ---------- launch ----------
extern "C" void kernel_launch(void* const* d_in, const int* in_sizes, int n_in,
                              void* d_out, int out_size){
    const float* gimage=(const float*)d_in[0];
    const int*   pts   =(const int*)  d_in[1];
    const float* gn1w=(const float*)d_in[2],  *gn1b=(const float*)d_in[3];
    const float* c1w =(const float*)d_in[4],  *c1b =(const float*)d_in[5];
    const float* gn2w=(const float*)d_in[6],  *gn2b=(const float*)d_in[7];
    const float* c2w =(const float*)d_in[8],  *c2b =(const float*)d_in[9];
    const float* clsw=(const float*)d_in[10], *clsb=(const float*)d_in[11];
    const float* mw1 =(const float*)d_in[12], *mb1 =(const float*)d_in[13];
    const float* mw2 =(const float*)d_in[14], *mb2 =(const float*)d_in[15];
    const float* mw3 =(const float*)d_in[16], *mb3 =(const float*)d_in[17];
    float* out=(float*)d_out;

    cudaFuncSetAttribute(main_kernel, cudaFuncAttributeMaxDynamicSharedMemorySize, SMEM_TOTAL);

    dim3 tgrid(HW/32, CH/32, BS), tblk(32,8);
    transpose_kernel<<<tgrid,tblk>>>(gimage);
    prep_kernel<<<384,256>>>(c1w,c2w,mw1,mw2);
    main_kernel<<<NBLK,256,SMEM_TOTAL>>>(pts,gn1w,gn1b,c1b,gn2w,gn2b,c2b,
                                         clsw,clsb,mb1,mb2,mw3,mb3,out);
}

// round 13
// speedup vs baseline: 5.7984x; 1.2564x over previous
#include <cuda_runtime.h>
#include <cuda_fp16.h>
#include <stdint.h>

#define HW 1024
#define CH 256
#define BS 32
#define NROWS 65536
#define MT 64
#define NBLK (NROWS/MT)

#define OFF_X   0                 // fp16 [64][264]
#define OFF_A   33792             // fp16 [64][264]
#define OFF_RED 67584             // 64*32 f32
#define OFF_W3  75776             // 1024 f32
#define OFF_CW  79872             // 512 f32
#define OFF_LIN 81920             // 64 ints
#define SMEM_TOTAL 82176

__device__ float g_t[(size_t)BS*HW*CH];                       // [b][p][c]
__device__ __align__(16) unsigned char g_wb[(size_t)6*8*16384]; // frag-packed fp16 weights

// ---------- helpers ----------
__device__ __forceinline__ uint32_t s2u(const void* p){
    uint32_t a; asm("{ .reg .u64 t; cvta.to.shared.u64 t, %1; cvt.u32.u64 %0, t; }":"=r"(a):"l"(p)); return a;
}
__device__ __forceinline__ uint32_t lds32(uint32_t a){
    uint32_t v; asm volatile("ld.shared.b32 %0,[%1];":"=r"(v):"r"(a)); return v;
}
__device__ __forceinline__ void sts32(uint32_t a,uint32_t v){
    asm volatile("st.shared.b32 [%0],%1;"::"r"(a),"r"(v));
}
__device__ __forceinline__ void ldsm4(uint32_t addr,uint32_t* r){
    asm volatile("ldmatrix.sync.aligned.m8n8.x4.shared.b16 {%0,%1,%2,%3}, [%4];"
        : "=r"(r[0]),"=r"(r[1]),"=r"(r[2]),"=r"(r[3]) : "r"(addr));
}
__device__ __forceinline__ float silu(float x){ return __fdividef(x,1.f+__expf(-x)); }
__device__ __forceinline__ uint32_t packh2(float f0,float f1){
    __half2 h=__floats2half2_rn(f0,f1); return *(uint32_t*)&h;
}
__device__ __forceinline__ float2 unph2(uint32_t u){
    return __half22float2(*(__half2*)&u);
}
__device__ __forceinline__ void mma16816(float* d,const uint32_t* a,uint32_t b0,uint32_t b1){
    asm volatile("mma.sync.aligned.m16n8k16.row.col.f32.f16.f16.f32 "
        "{%0,%1,%2,%3}, {%4,%5,%6,%7}, {%8,%9}, {%0,%1,%2,%3};"
        : "+f"(d[0]),"+f"(d[1]),"+f"(d[2]),"+f"(d[3])
        : "r"(a[0]),"r"(a[1]),"r"(a[2]),"r"(a[3]),"r"(b0),"r"(b1));
}
// GN over 8 channels spread across the 4 quad lanes (2 per lane)
#define GNPAIR(D0,D1,GW,GB,N0) { \
    float s_=(D0)+(D1); s_+=__shfl_xor_sync(0xffffffffu,s_,1); s_+=__shfl_xor_sync(0xffffffffu,s_,2); \
    float mn_=s_*0.125f, e0_=(D0)-mn_, e1_=(D1)-mn_; \
    float vv_=e0_*e0_+e1_*e1_; vv_+=__shfl_xor_sync(0xffffffffu,vv_,1); vv_+=__shfl_xor_sync(0xffffffffu,vv_,2); \
    float rs_=rsqrtf(vv_*0.125f+1e-5f); \
    (D0)=silu(e0_*rs_*(GW)[N0]+(GB)[N0]); (D1)=silu(e1_*rs_*(GW)[(N0)+1]+(GB)[(N0)+1]); }

// ---------- kernel 1: transpose [b][c][p] -> [b][p][c] ----------
__global__ void transpose_kernel(const float* __restrict__ g){
    __shared__ float tile[32][33];
    int b=blockIdx.z, p0=blockIdx.x*32, c0=blockIdx.y*32;
    int tx=threadIdx.x, ty=threadIdx.y;
    const float* src=g+(size_t)b*CH*HW;
    float* dst=g_t+(size_t)b*HW*CH;
#pragma unroll
    for(int i=0;i<4;i++) tile[ty+i*8][tx]=src[(size_t)(c0+ty+i*8)*HW+p0+tx];
    __syncthreads();
#pragma unroll
    for(int i=0;i<4;i++) dst[(size_t)(p0+ty+i*8)*CH+c0+tx]=tile[tx][ty+i*8];
}

// ---------- kernel 2: weights -> fp16 fragment-packed, lane-major 32B -------
// chunk (w,kc)=16KB; within: ks*8192 + nh*1024 + lane*32 + lt*8
__global__ void prep_kernel(const float* __restrict__ c1,const float* __restrict__ c2,
                            const float* __restrict__ m1,const float* __restrict__ m2){
    int gid=blockIdx.x*256+threadIdx.x;          // 98304 total
    int lane=gid&31, nt=(gid>>5)&31, ks=(gid>>10)&1, kc=(gid>>11)&7, w=gid>>14;
    int q=lane&3, g=lane>>2;
    int nh=nt>>2, lt=nt&3;
    int n=nt*8+g;
    int k0=kc*32+ks*16+q*2;
    float v0,v1,v2,v3;
    if(w<4){
        const float* s=(w&1)?c2:c1; int L=w>>1;
        const float* p=s+((size_t)(L*CH+n)*CH)*9+4;
        v0=p[(size_t)k0*9]; v1=p[(size_t)(k0+1)*9];
        v2=p[(size_t)(k0+8)*9]; v3=p[(size_t)(k0+9)*9];
    } else {
        const float* p=((w==4)?m1:m2)+(size_t)n*CH;
        v0=p[k0]; v1=p[k0+1]; v2=p[k0+8]; v3=p[k0+9];
    }
    size_t base=(size_t)(w*8+kc)*16384;
    uint32_t fo=(uint32_t)(ks*8192+nh*1024+lane*32+lt*8);
    *(uint2*)(g_wb+base+fo)=make_uint2(packh2(v0,v1),packh2(v2,v3));
}

// ---------- GEMM: D[64][256] = A[64][256] x W^T; B LDG.128 depth-3 ----------
// warp nh owns all 4 m-frags x 4 n-tiles (cols nh*32..nh*32+31).
__device__ __forceinline__ void run_gemm(int w,uint32_t smb,int nh,int lane,
                                         float d[16][4]){
#pragma unroll
    for(int i=0;i<16;i++){d[i][0]=0.f;d[i][1]=0.f;d[i][2]=0.f;d[i][3]=0.f;}
    const unsigned char* wb=g_wb+(size_t)w*131072;
    uint32_t lo=((uint32_t)nh<<10)+((uint32_t)lane<<5);   // nh*1024 + lane*32
    uint32_t abase=smb+OFF_A+(uint32_t)(lane&15)*528+((lane&16)?16u:0u);
    uint4 bp[3][2];
#pragma unroll
    for(int s=0;s<3;s++){
        const unsigned char* src=wb+(s>>1)*16384+(s&1)*8192+lo;
        bp[s][0]=__ldg((const uint4*)(src));
        bp[s][1]=__ldg((const uint4*)(src+16));
    }
#pragma unroll
    for(int kst=0;kst<16;kst++){
        uint4 b01=bp[kst%3][0], b23=bp[kst%3][1];
        if(kst<13){
            int kn=kst+3;
            const unsigned char* src=wb+(kn>>1)*16384+(kn&1)*8192+lo;
            bp[kst%3][0]=__ldg((const uint4*)(src));
            bp[kst%3][1]=__ldg((const uint4*)(src+16));
        }
        uint32_t ak=abase+(uint32_t)kst*32;
        uint32_t ah[4][4];
#pragma unroll
        for(int mf=0;mf<4;mf++) ldsm4(ak+(uint32_t)mf*(16*528),ah[mf]);
#pragma unroll
        for(int mf=0;mf<4;mf++){
            mma16816(d[mf*4+0],ah[mf],b01.x,b01.y);
            mma16816(d[mf*4+1],ah[mf],b01.z,b01.w);
            mma16816(d[mf*4+2],ah[mf],b23.x,b23.y);
            mma16816(d[mf*4+3],ah[mf],b23.z,b23.w);
        }
    }
}

// ---------- fused main kernel ----------
__global__ __launch_bounds__(256,2) void main_kernel(
    const int* __restrict__ pts,
    const float* __restrict__ gn1w,const float* __restrict__ gn1b,
    const float* __restrict__ c1b,
    const float* __restrict__ gn2w,const float* __restrict__ gn2b,
    const float* __restrict__ c2b,
    const float* __restrict__ clsw,const float* __restrict__ clsb,
    const float* __restrict__ mb1,const float* __restrict__ mb2,
    const float* __restrict__ mw3,const float* __restrict__ mb3,
    float* __restrict__ out)
{
    extern __shared__ __align__(16) unsigned char smp[];
    uint32_t smb=s2u(smp);
    int tid=threadIdx.x, lane=tid&31, nh=tid>>5;
    int g=lane>>2, q=lane&3;
    int row_base=blockIdx.x*MT;
    float* w3s=(float*)(smp+OFF_W3);
    float* cws=(float*)(smp+OFF_CW);
    float* red=(float*)(smp+OFF_RED);

    for(int i=tid;i<1024;i+=256) w3s[i]=mw3[i];
    for(int i=tid;i<512;i+=256)  cws[i]=clsw[i];
    if(tid<MT){
        int r=row_base+tid;
        int p0=pts[r*2], p1=pts[r*2+1];
        ((int*)(smp+OFF_LIN))[tid]=((r>>11)*HW+((p0>>3)*32+(p1>>3)))*CH;
    }
    __syncthreads();

    // gather -> X(fp16) ; GN1[0]+SiLU -> A(fp16)
    {
        int row=tid>>2, t4=tid&3;
        const float* src=g_t+((const int*)(smp+OFF_LIN))[row]+t4*64;
        float v[64];
#pragma unroll
        for(int i=0;i<16;i++) *(float4*)(v+i*4)=*(const float4*)(src+i*4);
        uint32_t xbb=smb+OFF_X+row*528+t4*128;
#pragma unroll
        for(int j2=0;j2<32;j2++) sts32(xbb+j2*4,packh2(v[2*j2],v[2*j2+1]));
#pragma unroll
        for(int gr=0;gr<8;gr++){
            float s=0.f,vv=0.f;
#pragma unroll
            for(int j=0;j<8;j++) s+=v[gr*8+j];
            float mean=s*0.125f;
#pragma unroll
            for(int j=0;j<8;j++){float e=v[gr*8+j]-mean; vv+=e*e;}
            float rs=rsqrtf(vv*0.125f+1e-5f);
#pragma unroll
            for(int j=0;j<8;j++){
                int n=t4*64+gr*8+j;
                v[gr*8+j]=silu((v[gr*8+j]-mean)*rs*gn1w[n]+gn1b[n]);
            }
        }
        uint32_t ahb=smb+OFF_A+row*528+t4*128;
#pragma unroll
        for(int j2=0;j2<32;j2++) sts32(ahb+j2*4,packh2(v[2*j2],v[2*j2+1]));
    }
    __syncthreads();

    float d[16][4];

#pragma unroll 1
    for(int L=0;L<2;++L){
        run_gemm(L*2+0,smb,nh,lane,d);                     // conv1
        __syncthreads();
        const float* b1=c1b+L*CH; const float* g2w=gn2w+L*CH; const float* g2b=gn2b+L*CH;
#pragma unroll
        for(int e=0;e<16;e++){
            int mf=e>>2, lt=e&3;
            int n0=nh*32+lt*8+q*2;
            uint32_t ro=(uint32_t)(mf*16+g)*528+(uint32_t)n0*2;
            d[e][0]+=b1[n0]; d[e][1]+=b1[n0+1]; d[e][2]+=b1[n0]; d[e][3]+=b1[n0+1];
            GNPAIR(d[e][0],d[e][1],g2w,g2b,n0);
            GNPAIR(d[e][2],d[e][3],g2w,g2b,n0);
            sts32(smb+OFF_A+ro,packh2(d[e][0],d[e][1]));
            sts32(smb+OFF_A+ro+8*528,packh2(d[e][2],d[e][3]));
        }
        __syncthreads();

        run_gemm(L*2+1,smb,nh,lane,d);                     // conv2
        __syncthreads();
        const float* b2=c2b+L*CH; const float* g1w=gn1w+CH; const float* g1b=gn1b+CH;
#pragma unroll
        for(int e=0;e<16;e++){
            int mf=e>>2, lt=e&3;
            int n0=nh*32+lt*8+q*2;
            uint32_t ro=(uint32_t)(mf*16+g)*528+(uint32_t)n0*2;
            float2 xf=unph2(lds32(smb+OFF_X+ro));
            d[e][0]+=b2[n0]+xf.x; d[e][1]+=b2[n0+1]+xf.y;
            sts32(smb+OFF_X+ro,packh2(d[e][0],d[e][1]));
            xf=unph2(lds32(smb+OFF_X+ro+8*528));
            d[e][2]+=b2[n0]+xf.x; d[e][3]+=b2[n0+1]+xf.y;
            sts32(smb+OFF_X+ro+8*528,packh2(d[e][2],d[e][3]));
            if(L==0){ GNPAIR(d[e][0],d[e][1],g1w,g1b,n0); GNPAIR(d[e][2],d[e][3],g1w,g1b,n0); }
            sts32(smb+OFF_A+ro,packh2(d[e][0],d[e][1]));
            sts32(smb+OFF_A+ro+8*528,packh2(d[e][2],d[e][3]));
        }
        __syncthreads();
    }

    run_gemm(4,smb,nh,lane,d);                             // mlp1
    __syncthreads();
#pragma unroll
    for(int e=0;e<16;e++){
        int mf=e>>2, lt=e&3;
        int n0=nh*32+lt*8+q*2;
        uint32_t ro=(uint32_t)(mf*16+g)*528+(uint32_t)n0*2;
        d[e][0]=fmaxf(d[e][0]+mb1[n0],0.f);   d[e][1]=fmaxf(d[e][1]+mb1[n0+1],0.f);
        d[e][2]=fmaxf(d[e][2]+mb1[n0],0.f);   d[e][3]=fmaxf(d[e][3]+mb1[n0+1],0.f);
        sts32(smb+OFF_A+ro,packh2(d[e][0],d[e][1]));
        sts32(smb+OFF_A+ro+8*528,packh2(d[e][2],d[e][3]));
    }
    __syncthreads();

    run_gemm(5,smb,nh,lane,d);                             // mlp2
    {
        float bxa[4][4], bxb[4][4];
#pragma unroll
        for(int mf=0;mf<4;mf++)
#pragma unroll
            for(int s=0;s<4;s++){ bxa[mf][s]=0.f; bxb[mf][s]=0.f; }
#pragma unroll
        for(int e=0;e<16;e++){
            int mf=e>>2, lt=e&3;
            int n0=nh*32+lt*8+q*2;
            float t0=fmaxf(d[e][0]+mb2[n0],0.f),  t1=fmaxf(d[e][1]+mb2[n0+1],0.f);
            float t2=fmaxf(d[e][2]+mb2[n0],0.f),  t3=fmaxf(d[e][3]+mb2[n0+1],0.f);
#pragma unroll
            for(int s=0;s<4;s++){
                float w0=w3s[s*256+n0], w1=w3s[s*256+n0+1];
                bxa[mf][s]+=t0*w0+t1*w1;
                bxb[mf][s]+=t2*w0+t3*w1;
            }
        }
#pragma unroll
        for(int mf=0;mf<4;mf++)
#pragma unroll
            for(int s=0;s<4;s++){
                bxa[mf][s]+=__shfl_xor_sync(0xffffffffu,bxa[mf][s],1);
                bxa[mf][s]+=__shfl_xor_sync(0xffffffffu,bxa[mf][s],2);
                bxb[mf][s]+=__shfl_xor_sync(0xffffffffu,bxb[mf][s],1);
                bxb[mf][s]+=__shfl_xor_sync(0xffffffffu,bxb[mf][s],2);
            }
        if(q==0){
#pragma unroll
            for(int mf=0;mf<4;mf++)
#pragma unroll
                for(int s=0;s<4;s++){
                    red[(mf*16+g)*32+nh*4+s]=bxa[mf][s];
                    red[(mf*16+g+8)*32+nh*4+s]=bxb[mf][s];
                }
        }
    }
    __syncthreads();

    // heads out
    if(tid<MT){
        size_t row=(size_t)row_base+tid;
#pragma unroll
        for(int s=0;s<4;s++){
            float a=mb3[s];
#pragma unroll
            for(int h=0;h<8;h++) a+=red[tid*32+h*4+s];
            out[131072+row*4+s]=__fdividef(1.f,1.f+__expf(-a));
        }
    }
    {
        int row=tid>>2, t4=tid&3;
        uint32_t xbb=smb+OFF_X+row*528+t4*128;
        float c0=0.f,c1=0.f;
#pragma unroll 8
        for(int j=0;j<32;j++){
            float2 xf=unph2(lds32(xbb+j*4));
            int k=t4*64+j*2;
            c0+=xf.x*cws[k]+xf.y*cws[k+1];
            c1+=xf.x*cws[256+k]+xf.y*cws[256+k+1];
        }
        c0+=__shfl_xor_sync(0xffffffffu,c0,1); c0+=__shfl_xor_sync(0xffffffffu,c0,2);
        c1+=__shfl_xor_sync(0xffffffffu,c1,1); c1+=__shfl_xor_sync(0xffffffffu,c1,2);
        if(t4==0){
            size_t r=(size_t)row_base+row;
            out[r*2+0]=c0+clsb[0];
            out[r*2+1]=c1+clsb[1];
        }
    }
}

// ---------- launch ----------
extern "C" void kernel_launch(void* const* d_in, const int* in_sizes, int n_in,
                              void* d_out, int out_size){
    const float* gimage=(const float*)d_in[0];
    const int*   pts   =(const int*)  d_in[1];
    const float* gn1w=(const float*)d_in[2],  *gn1b=(const float*)d_in[3];
    const float* c1w =(const float*)d_in[4],  *c1b =(const float*)d_in[5];
    const float* gn2w=(const float*)d_in[6],  *gn2b=(const float*)d_in[7];
    const float* c2w =(const float*)d_in[8],  *c2b =(const float*)d_in[9];
    const float* clsw=(const float*)d_in[10], *clsb=(const float*)d_in[11];
    const float* mw1 =(const float*)d_in[12], *mb1 =(const float*)d_in[13];
    const float* mw2 =(const float*)d_in[14], *mb2 =(const float*)d_in[15];
    const float* mw3 =(const float*)d_in[16], *mb3 =(const float*)d_in[17];
    float* out=(float*)d_out;

    cudaFuncSetAttribute(main_kernel, cudaFuncAttributeMaxDynamicSharedMemorySize, SMEM_TOTAL);

    dim3 tgrid(HW/32, CH/32, BS), tblk(32,8);
    transpose_kernel<<<tgrid,tblk>>>(gimage);
    prep_kernel<<<384,256>>>(c1w,c2w,mw1,mw2);
    main_kernel<<<NBLK,256,SMEM_TOTAL>>>(pts,gn1w,gn1b,c1b,gn2w,gn2b,c2b,
                                         clsw,clsb,mb1,mb2,mw3,mb3,out);
}

// round 14
// speedup vs baseline: 6.2298x; 1.0744x over previous
#include <cuda_runtime.h>
#include <cuda_fp16.h>
#include <stdint.h>

#define HW 1024
#define CH 256
#define BS 32
#define NROWS 65536
#define MT 64
#define NBLK (NROWS/MT)

#define OFF_X   0                 // fp16 [64][264] (permuted cols)
#define OFF_A   33792             // fp16 [64][264] (permuted cols)
#define OFF_RED 67584             // 64*32 f32
#define OFF_W3  75776             // 1024 f32 (permuted)
#define OFF_CW  79872             // 512 f32 (permuted)
#define OFF_LIN 81920             // 64 ints
#define SMEM_TOTAL 82176

__device__ float g_t[(size_t)BS*HW*CH];                       // [b][p][c]
__device__ __align__(16) unsigned char g_wb[(size_t)6*8*16384]; // frag-packed fp16 weights

// channel permutation (involution): logical <-> physical MMA column
__device__ __forceinline__ int chperm(int c){
    return (c&~31)|(((c>>1)&3)<<3)|(((c>>3)&3)<<1)|(c&1);
}

// ---------- helpers ----------
__device__ __forceinline__ uint32_t s2u(const void* p){
    uint32_t a; asm("{ .reg .u64 t; cvta.to.shared.u64 t, %1; cvt.u32.u64 %0, t; }":"=r"(a):"l"(p)); return a;
}
__device__ __forceinline__ uint32_t lds32(uint32_t a){
    uint32_t v; asm volatile("ld.shared.b32 %0,[%1];":"=r"(v):"r"(a)); return v;
}
__device__ __forceinline__ void sts32(uint32_t a,uint32_t v){
    asm volatile("st.shared.b32 [%0],%1;"::"r"(a),"r"(v));
}
__device__ __forceinline__ void ldsm4(uint32_t addr,uint32_t* r){
    asm volatile("ldmatrix.sync.aligned.m8n8.x4.shared.b16 {%0,%1,%2,%3}, [%4];"
        : "=r"(r[0]),"=r"(r[1]),"=r"(r[2]),"=r"(r[3]) : "r"(addr));
}
__device__ __forceinline__ float silu(float x){ return __fdividef(x,1.f+__expf(-x)); }
__device__ __forceinline__ uint32_t packh2(float f0,float f1){
    __half2 h=__floats2half2_rn(f0,f1); return *(uint32_t*)&h;
}
__device__ __forceinline__ float2 unph2(uint32_t u){
    return __half22float2(*(__half2*)&u);
}
__device__ __forceinline__ void mma16816(float* d,const uint32_t* a,uint32_t b0,uint32_t b1){
    asm volatile("mma.sync.aligned.m16n8k16.row.col.f32.f16.f16.f32 "
        "{%0,%1,%2,%3}, {%4,%5,%6,%7}, {%8,%9}, {%0,%1,%2,%3};"
        : "+f"(d[0]),"+f"(d[1]),"+f"(d[2]),"+f"(d[3])
        : "r"(a[0]),"r"(a[1]),"r"(a[2]),"r"(a[3]),"r"(b0),"r"(b1));
}

// ---------- kernel 1: transpose [b][c][p] -> [b][p][c] ----------
__global__ void transpose_kernel(const float* __restrict__ g){
    __shared__ float tile[32][33];
    int b=blockIdx.z, p0=blockIdx.x*32, c0=blockIdx.y*32;
    int tx=threadIdx.x, ty=threadIdx.y;
    const float* src=g+(size_t)b*CH*HW;
    float* dst=g_t+(size_t)b*HW*CH;
#pragma unroll
    for(int i=0;i<4;i++) tile[ty+i*8][tx]=src[(size_t)(c0+ty+i*8)*HW+p0+tx];
    __syncthreads();
#pragma unroll
    for(int i=0;i<4;i++) dst[(size_t)(p0+ty+i*8)*CH+c0+tx]=tile[tx][ty+i*8];
}

// ---------- kernel 2: weights -> fp16 fragments, permuted n and k ----------
__global__ void prep_kernel(const float* __restrict__ c1,const float* __restrict__ c2,
                            const float* __restrict__ m1,const float* __restrict__ m2){
    int gid=blockIdx.x*256+threadIdx.x;          // 98304 total
    int lane=gid&31, nt=(gid>>5)&31, ks=(gid>>10)&1, kc=(gid>>11)&7, w=gid>>14;
    int q=lane&3, g=lane>>2;
    int nh=nt>>2, lt=nt&3;
    int n_l=chperm(nt*8+g);
    int k0=kc*32+ks*16+q*2;
    int kl0=chperm(k0), kl2=chperm(k0+8);
    float v0,v1,v2,v3;
    if(w<4){
        const float* s=(w&1)?c2:c1; int L=w>>1;
        const float* p=s+((size_t)(L*CH+n_l)*CH)*9+4;
        v0=p[(size_t)kl0*9]; v1=p[(size_t)(kl0+1)*9];
        v2=p[(size_t)kl2*9]; v3=p[(size_t)(kl2+1)*9];
    } else {
        const float* p=((w==4)?m1:m2)+(size_t)n_l*CH;
        v0=p[kl0]; v1=p[kl0+1]; v2=p[kl2]; v3=p[kl2+1];
    }
    size_t base=(size_t)(w*8+kc)*16384;
    uint32_t fo=(uint32_t)(ks*8192+nh*1024+lane*32+lt*8);
    *(uint2*)(g_wb+base+fo)=make_uint2(packh2(v0,v1),packh2(v2,v3));
}

// ---------- GEMM: D[64][256] = A[64][256] x W^T; B LDG.128 depth-3 ----------
__device__ __forceinline__ void run_gemm(int w,uint32_t smb,int nh,int lane,
                                         float d[16][4]){
#pragma unroll
    for(int i=0;i<16;i++){d[i][0]=0.f;d[i][1]=0.f;d[i][2]=0.f;d[i][3]=0.f;}
    const unsigned char* wb=g_wb+(size_t)w*131072;
    uint32_t lo=((uint32_t)nh<<10)+((uint32_t)lane<<5);
    uint32_t abase=smb+OFF_A+(uint32_t)(lane&15)*528+((lane&16)?16u:0u);
    uint4 bp[3][2];
#pragma unroll
    for(int s=0;s<3;s++){
        const unsigned char* src=wb+(s>>1)*16384+(s&1)*8192+lo;
        bp[s][0]=__ldg((const uint4*)(src));
        bp[s][1]=__ldg((const uint4*)(src+16));
    }
#pragma unroll
    for(int kst=0;kst<16;kst++){
        uint4 b01=bp[kst%3][0], b23=bp[kst%3][1];
        if(kst<13){
            int kn=kst+3;
            const unsigned char* src=wb+(kn>>1)*16384+(kn&1)*8192+lo;
            bp[kst%3][0]=__ldg((const uint4*)(src));
            bp[kst%3][1]=__ldg((const uint4*)(src+16));
        }
        uint32_t ak=abase+(uint32_t)kst*32;
        uint32_t ah[4][4];
#pragma unroll
        for(int mf=0;mf<4;mf++) ldsm4(ak+(uint32_t)mf*(16*528),ah[mf]);
#pragma unroll
        for(int mf=0;mf<4;mf++){
            mma16816(d[mf*4+0],ah[mf],b01.x,b01.y);
            mma16816(d[mf*4+1],ah[mf],b01.z,b01.w);
            mma16816(d[mf*4+2],ah[mf],b23.x,b23.y);
            mma16816(d[mf*4+3],ah[mf],b23.z,b23.w);
        }
    }
}

// thread-local GN+SiLU over the 8 cols (one group) a quad-lane owns, one row
#define GN8(MF,I0,GW,GB,LB) { \
    float s_=0.f; \
    _Pragma("unroll") for(int lt_=0;lt_<4;lt_++) s_+=d[(MF)*4+lt_][I0]+d[(MF)*4+lt_][(I0)+1]; \
    float mn_=s_*0.125f, vv_=0.f; \
    _Pragma("unroll") for(int lt_=0;lt_<4;lt_++){ \
        float e0_=d[(MF)*4+lt_][I0]-mn_, e1_=d[(MF)*4+lt_][(I0)+1]-mn_; vv_+=e0_*e0_+e1_*e1_; } \
    float rs_=rsqrtf(vv_*0.125f+1e-5f); \
    _Pragma("unroll") for(int lt_=0;lt_<4;lt_++){ \
        int l_=(LB)+lt_*2; \
        d[(MF)*4+lt_][I0]    =silu((d[(MF)*4+lt_][I0]    -mn_)*rs_*(GW)[l_]  +(GB)[l_]); \
        d[(MF)*4+lt_][(I0)+1]=silu((d[(MF)*4+lt_][(I0)+1]-mn_)*rs_*(GW)[l_+1]+(GB)[l_+1]); } }

// ---------- fused main kernel ----------
__global__ __launch_bounds__(256,2) void main_kernel(
    const int* __restrict__ pts,
    const float* __restrict__ gn1w,const float* __restrict__ gn1b,
    const float* __restrict__ c1b,
    const float* __restrict__ gn2w,const float* __restrict__ gn2b,
    const float* __restrict__ c2b,
    const float* __restrict__ clsw,const float* __restrict__ clsb,
    const float* __restrict__ mb1,const float* __restrict__ mb2,
    const float* __restrict__ mw3,const float* __restrict__ mb3,
    float* __restrict__ out)
{
    extern __shared__ __align__(16) unsigned char smp[];
    uint32_t smb=s2u(smp);
    int tid=threadIdx.x, lane=tid&31, nh=tid>>5;
    int g=lane>>2, q=lane&3;
    int row_base=blockIdx.x*MT;
    float* w3s=(float*)(smp+OFF_W3);
    float* cws=(float*)(smp+OFF_CW);
    float* red=(float*)(smp+OFF_RED);

    for(int i=tid;i<1024;i+=256) w3s[i]=mw3[(i&~255)+chperm(i&255)];
    for(int i=tid;i<512;i+=256)  cws[i]=clsw[(i&~255)+chperm(i&255)];
    if(tid<MT){
        int r=row_base+tid;
        int p0=pts[r*2], p1=pts[r*2+1];
        ((int*)(smp+OFF_LIN))[tid]=((r>>11)*HW+((p0>>3)*32+(p1>>3)))*CH;
    }
    __syncthreads();

    // gather -> X(fp16, permuted) ; GN1[0]+SiLU -> A(fp16, permuted)
    {
        int row=tid>>2, t4=tid&3;
        const float* src=g_t+((const int*)(smp+OFF_LIN))[row]+t4*64;
        float v[64];
#pragma unroll
        for(int i=0;i<16;i++) *(float4*)(v+i*4)=*(const float4*)(src+i*4);
        uint32_t xrb=smb+OFF_X+row*528;
#pragma unroll
        for(int j2=0;j2<32;j2++){
            int p=chperm(t4*64+j2*2);
            sts32(xrb+p*2,packh2(v[2*j2],v[2*j2+1]));
        }
#pragma unroll
        for(int gr=0;gr<8;gr++){
            float s=0.f,vv=0.f;
#pragma unroll
            for(int j=0;j<8;j++) s+=v[gr*8+j];
            float mean=s*0.125f;
#pragma unroll
            for(int j=0;j<8;j++){float e=v[gr*8+j]-mean; vv+=e*e;}
            float rs=rsqrtf(vv*0.125f+1e-5f);
#pragma unroll
            for(int j=0;j<8;j++){
                int n=t4*64+gr*8+j;
                v[gr*8+j]=silu((v[gr*8+j]-mean)*rs*gn1w[n]+gn1b[n]);
            }
        }
        uint32_t arb=smb+OFF_A+row*528;
#pragma unroll
        for(int j2=0;j2<32;j2++){
            int p=chperm(t4*64+j2*2);
            sts32(arb+p*2,packh2(v[2*j2],v[2*j2+1]));
        }
    }
    __syncthreads();

    float d[16][4];
    int lb=nh*32+q*8;   // logical channel base for this quad lane

#pragma unroll 1
    for(int L=0;L<2;++L){
        run_gemm(L*2+0,smb,nh,lane,d);                     // conv1
        __syncthreads();
        {
            const float* b1=c1b+L*CH; const float* g2w=gn2w+L*CH; const float* g2b=gn2b+L*CH;
#pragma unroll
            for(int mf=0;mf<4;mf++){
#pragma unroll
                for(int lt=0;lt<4;lt++){
                    float bb0=b1[lb+lt*2], bb1=b1[lb+lt*2+1];
                    d[mf*4+lt][0]+=bb0; d[mf*4+lt][1]+=bb1;
                    d[mf*4+lt][2]+=bb0; d[mf*4+lt][3]+=bb1;
                }
                GN8(mf,0,g2w,g2b,lb);
                GN8(mf,2,g2w,g2b,lb);
#pragma unroll
                for(int lt=0;lt<4;lt++){
                    uint32_t ro=(uint32_t)(mf*16+g)*528+(uint32_t)(nh*32+lt*8+q*2)*2;
                    sts32(smb+OFF_A+ro,packh2(d[mf*4+lt][0],d[mf*4+lt][1]));
                    sts32(smb+OFF_A+ro+8*528,packh2(d[mf*4+lt][2],d[mf*4+lt][3]));
                }
            }
        }
        __syncthreads();

        run_gemm(L*2+1,smb,nh,lane,d);                     // conv2
        __syncthreads();
        {
            const float* b2=c2b+L*CH; const float* g1w=gn1w+CH; const float* g1b=gn1b+CH;
#pragma unroll
            for(int mf=0;mf<4;mf++){
#pragma unroll
                for(int lt=0;lt<4;lt++){
                    uint32_t ro=(uint32_t)(mf*16+g)*528+(uint32_t)(nh*32+lt*8+q*2)*2;
                    float bb0=b2[lb+lt*2], bb1=b2[lb+lt*2+1];
                    float2 xf=unph2(lds32(smb+OFF_X+ro));
                    d[mf*4+lt][0]+=bb0+xf.x; d[mf*4+lt][1]+=bb1+xf.y;
                    sts32(smb+OFF_X+ro,packh2(d[mf*4+lt][0],d[mf*4+lt][1]));
                    xf=unph2(lds32(smb+OFF_X+ro+8*528));
                    d[mf*4+lt][2]+=bb0+xf.x; d[mf*4+lt][3]+=bb1+xf.y;
                    sts32(smb+OFF_X+ro+8*528,packh2(d[mf*4+lt][2],d[mf*4+lt][3]));
                }
                if(L==0){ GN8(mf,0,g1w,g1b,lb); GN8(mf,2,g1w,g1b,lb); }
#pragma unroll
                for(int lt=0;lt<4;lt++){
                    uint32_t ro=(uint32_t)(mf*16+g)*528+(uint32_t)(nh*32+lt*8+q*2)*2;
                    sts32(smb+OFF_A+ro,packh2(d[mf*4+lt][0],d[mf*4+lt][1]));
                    sts32(smb+OFF_A+ro+8*528,packh2(d[mf*4+lt][2],d[mf*4+lt][3]));
                }
            }
        }
        __syncthreads();
    }

    run_gemm(4,smb,nh,lane,d);                             // mlp1
    __syncthreads();
#pragma unroll
    for(int e=0;e<16;e++){
        int mf=e>>2, lt=e&3;
        float bb0=mb1[lb+lt*2], bb1=mb1[lb+lt*2+1];
        uint32_t ro=(uint32_t)(mf*16+g)*528+(uint32_t)(nh*32+lt*8+q*2)*2;
        d[e][0]=fmaxf(d[e][0]+bb0,0.f);   d[e][1]=fmaxf(d[e][1]+bb1,0.f);
        d[e][2]=fmaxf(d[e][2]+bb0,0.f);   d[e][3]=fmaxf(d[e][3]+bb1,0.f);
        sts32(smb+OFF_A+ro,packh2(d[e][0],d[e][1]));
        sts32(smb+OFF_A+ro+8*528,packh2(d[e][2],d[e][3]));
    }
    __syncthreads();

    run_gemm(5,smb,nh,lane,d);                             // mlp2
    {
        float bxa[4][4], bxb[4][4];
#pragma unroll
        for(int mf=0;mf<4;mf++)
#pragma unroll
            for(int s=0;s<4;s++){ bxa[mf][s]=0.f; bxb[mf][s]=0.f; }
#pragma unroll
        for(int e=0;e<16;e++){
            int mf=e>>2, lt=e&3;
            int n0=nh*32+lt*8+q*2;
            float bb0=mb2[lb+lt*2], bb1=mb2[lb+lt*2+1];
            float t0=fmaxf(d[e][0]+bb0,0.f),  t1=fmaxf(d[e][1]+bb1,0.f);
            float t2=fmaxf(d[e][2]+bb0,0.f),  t3=fmaxf(d[e][3]+bb1,0.f);
#pragma unroll
            for(int s=0;s<4;s++){
                float w0=w3s[s*256+n0], w1=w3s[s*256+n0+1];
                bxa[mf][s]+=t0*w0+t1*w1;
                bxb[mf][s]+=t2*w0+t3*w1;
            }
        }
#pragma unroll
        for(int mf=0;mf<4;mf++)
#pragma unroll
            for(int s=0;s<4;s++){
                bxa[mf][s]+=__shfl_xor_sync(0xffffffffu,bxa[mf][s],1);
                bxa[mf][s]+=__shfl_xor_sync(0xffffffffu,bxa[mf][s],2);
                bxb[mf][s]+=__shfl_xor_sync(0xffffffffu,bxb[mf][s],1);
                bxb[mf][s]+=__shfl_xor_sync(0xffffffffu,bxb[mf][s],2);
            }
        if(q==0){
#pragma unroll
            for(int mf=0;mf<4;mf++)
#pragma unroll
                for(int s=0;s<4;s++){
                    red[(mf*16+g)*32+nh*4+s]=bxa[mf][s];
                    red[(mf*16+g+8)*32+nh*4+s]=bxb[mf][s];
                }
        }
    }
    __syncthreads();

    // heads out
    if(tid<MT){
        size_t row=(size_t)row_base+tid;
#pragma unroll
        for(int s=0;s<4;s++){
            float a=mb3[s];
#pragma unroll
            for(int h=0;h<8;h++) a+=red[tid*32+h*4+s];
            out[131072+row*4+s]=__fdividef(1.f,1.f+__expf(-a));
        }
    }
    {
        int row=tid>>2, t4=tid&3;
        uint32_t xbb=smb+OFF_X+row*528+t4*128;
        float c0=0.f,c1=0.f;
#pragma unroll 8
        for(int j=0;j<32;j++){
            float2 xf=unph2(lds32(xbb+j*4));
            int k=t4*64+j*2;
            c0+=xf.x*cws[k]+xf.y*cws[k+1];
            c1+=xf.x*cws[256+k]+xf.y*cws[256+k+1];
        }
        c0+=__shfl_xor_sync(0xffffffffu,c0,1); c0+=__shfl_xor_sync(0xffffffffu,c0,2);
        c1+=__shfl_xor_sync(0xffffffffu,c1,1); c1+=__shfl_xor_sync(0xffffffffu,c1,2);
        if(t4==0){
            size_t r=(size_t)row_base+row;
            out[r*2+0]=c0+clsb[0];
            out[r*2+1]=c1+clsb[1];
        }
    }
}

// ---------- launch ----------
extern "C" void kernel_launch(void* const* d_in, const int* in_sizes, int n_in,
                              void* d_out, int out_size){
    const float* gimage=(const float*)d_in[0];
    const int*   pts   =(const int*)  d_in[1];
    const float* gn1w=(const float*)d_in[2],  *gn1b=(const float*)d_in[3];
    const float* c1w =(const float*)d_in[4],  *c1b =(const float*)d_in[5];
    const float* gn2w=(const float*)d_in[6],  *gn2b=(const float*)d_in[7];
    const float* c2w =(const float*)d_in[8],  *c2b =(const float*)d_in[9];
    const float* clsw=(const float*)d_in[10], *clsb=(const float*)d_in[11];
    const float* mw1 =(const float*)d_in[12], *mb1 =(const float*)d_in[13];
    const float* mw2 =(const float*)d_in[14], *mb2 =(const float*)d_in[15];
    const float* mw3 =(const float*)d_in[16], *mb3 =(const float*)d_in[17];
    float* out=(float*)d_out;

    cudaFuncSetAttribute(main_kernel, cudaFuncAttributeMaxDynamicSharedMemorySize, SMEM_TOTAL);

    dim3 tgrid(HW/32, CH/32, BS), tblk(32,8);
    transpose_kernel<<<tgrid,tblk>>>(gimage);
    prep_kernel<<<384,256>>>(c1w,c2w,mw1,mw2);
    main_kernel<<<NBLK,256,SMEM_TOTAL>>>(pts,gn1w,gn1b,c1b,gn2w,gn2b,c2b,
                                         clsw,clsb,mb1,mb2,mw3,mb3,out);
}